// round 3
// baseline (speedup 1.0000x reference)
#include <cuda_runtime.h>
#include <cuda_bf16.h>
#include <cstdint>
#include <math.h>

// ===================== problem constants =====================
#define BB 4
#define TT 256
#define UU 128
#define ENC_H 512
#define PRED_H 640
#define JH 640
#define VC 1025            // real classes
#define VP 1152            // padded classes (9 * 128)
#define NCHUNK 9
#define NC 128             // classes per chunk
#define NSLICE 10          // K slices of 64 per chunk

// ===================== device scratch ========================
__device__ float f_dev[BB*TT*JH];
__device__ float g_dev[BB*UU*JH];
__device__ __nv_bfloat16 w_dev[VP*JH];

// ===================== helpers ===========================
__device__ __forceinline__ uint32_t smem_to_u32(const void* p) {
    uint32_t a;
    asm("{ .reg .u64 t; cvta.to.shared.u64 t, %1; cvt.u32.u64 %0, t; }" : "=r"(a) : "l"(p));
    return a;
}
__device__ __forceinline__ uint32_t pack_bf16x2(float lo, float hi) {
    uint32_t p;
    asm("cvt.rn.bf16x2.f32 %0, %1, %2;" : "=r"(p) : "f"(hi), "f"(lo));
    return p;
}
__device__ __forceinline__ void ldsm_x4(uint32_t& r0, uint32_t& r1, uint32_t& r2, uint32_t& r3, uint32_t addr) {
    asm volatile("ldmatrix.sync.aligned.m8n8.x4.shared.b16 {%0,%1,%2,%3}, [%4];"
        : "=r"(r0), "=r"(r1), "=r"(r2), "=r"(r3) : "r"(addr));
}
__device__ __forceinline__ void ldsm_x2(uint32_t& r0, uint32_t& r1, uint32_t addr) {
    asm volatile("ldmatrix.sync.aligned.m8n8.x2.shared.b16 {%0,%1}, [%2];"
        : "=r"(r0), "=r"(r1) : "r"(addr));
}
__device__ __forceinline__ void mma16816(float* d, const uint32_t* a, const uint32_t* b) {
    asm volatile("mma.sync.aligned.m16n8k16.row.col.f32.bf16.bf16.f32 "
        "{%0,%1,%2,%3}, {%4,%5,%6,%7}, {%8,%9}, {%0,%1,%2,%3};"
        : "+f"(d[0]), "+f"(d[1]), "+f"(d[2]), "+f"(d[3])
        : "r"(a[0]), "r"(a[1]), "r"(a[2]), "r"(a[3]), "r"(b[0]), "r"(b[1]));
}
__device__ __forceinline__ void cp_async16(uint32_t saddr, const void* gaddr) {
    asm volatile("cp.async.cg.shared.global [%0], [%1], 16;" :: "r"(saddr), "l"(gaddr));
}
__device__ __forceinline__ void cp_commit() { asm volatile("cp.async.commit_group;"); }
__device__ __forceinline__ void cp_wait1() { asm volatile("cp.async.wait_group 1;"); }
__device__ __forceinline__ void cp_wait0() { asm volatile("cp.async.wait_group 0;"); }

// SMEM swizzled addressing (16B chunk granularity, XOR row&7)
__device__ __forceinline__ uint32_t a_addr(uint32_t base, int row, int chunk) {
    int sc = (chunk & ~7) | ((chunk & 7) ^ (row & 7));
    return base + (uint32_t)(row * 1280 + sc * 16);
}
__device__ __forceinline__ uint32_t b_addr(uint32_t base, int n, int chunk) {
    return base + (uint32_t)(n * 128 + ((chunk ^ n) & 7) * 16);
}

// ===================== SMEM layout (relative to 1KB-aligned base) ==========
#define A_OFF      0                   // 128 x 640 bf16 swizzled: 163840 B
#define B0_OFF     163840              // 128 x 64 bf16 swizzled: 16384 B
#define B1_OFF     180224              // second buffer
#define BIAS_OFF   196608              // 1152 fp32
#define F_OFF      201216              // 640 fp32
#define RED_OFF    203776              // 4 x 128 fp32
#define LSE_OFF    205824              // 128 fp32
#define SMEM_USED  206336
#define DYN_SMEM   (SMEM_USED + 1024)

// ===================== small projection GEMM (f and g) ======================
__global__ void proj_kernel(const float* __restrict__ X, const float* __restrict__ W,
                            const float* __restrict__ bias, float* __restrict__ Out,
                            int H, int R) {
    __shared__ float Xs[32*33];
    __shared__ float Ws[32*65];
    int r0 = blockIdx.x * 32, j0 = blockIdx.y * 64, b = blockIdx.z;
    int tid = threadIdx.x;
    int r = tid & 31, jg = tid >> 5;
    float acc[8];
#pragma unroll
    for (int i = 0; i < 8; i++) acc[i] = 0.f;
    const float* Xb = X + (size_t)b * H * R;
    for (int h0 = 0; h0 < H; h0 += 32) {
        for (int i = tid; i < 32*32; i += 256) {
            int hh = i >> 5, rr = i & 31;
            Xs[hh*33 + rr] = Xb[(size_t)(h0 + hh) * R + r0 + rr];
        }
        for (int i = tid; i < 64*32; i += 256) {
            int jj = i >> 5, hh = i & 31;
            Ws[hh*65 + jj] = W[(size_t)(j0 + jj) * H + h0 + hh];
        }
        __syncthreads();
#pragma unroll
        for (int hh = 0; hh < 32; hh++) {
            float x = Xs[hh*33 + r];
#pragma unroll
            for (int jj = 0; jj < 8; jj++)
                acc[jj] = fmaf(x, Ws[hh*65 + jg*8 + jj], acc[jj]);
        }
        __syncthreads();
    }
    float* o = Out + ((size_t)b * R + r0 + r) * JH + j0 + jg*8;
#pragma unroll
    for (int jj = 0; jj < 8; jj++) o[jj] = acc[jj] + bias[j0 + jg*8 + jj];
}

// ===================== W_joint fp32 -> bf16 (padded) ========================
__global__ void wconv_kernel(const float* __restrict__ Wj) {
    int idx = blockIdx.x * 256 + threadIdx.x;
    if (idx >= VP * JH) return;
    float v = (idx < VC * JH) ? Wj[idx] : 0.f;
    w_dev[idx] = __float2bfloat16(v);
}

// ===================== fused joint GEMM + log_softmax ======================
__global__ void __launch_bounds__(256, 1)
joint_kernel(const float* __restrict__ b_joint, float* __restrict__ out) {
    extern __shared__ char smraw[];
    uint32_t sm_u = smem_to_u32(smraw);
    uint32_t pad = ((sm_u + 1023) & ~1023u) - sm_u;
    char* sb = smraw + pad;
    uint32_t sb_u = sm_u + pad;

    float* bias_s = (float*)(sb + BIAS_OFF);
    float* f_s    = (float*)(sb + F_OFF);
    float* red    = (float*)(sb + RED_OFF);
    float* lse_s  = (float*)(sb + LSE_OFF);
    uint32_t a_base  = sb_u + A_OFF;
    uint32_t b_base[2] = { sb_u + B0_OFF, sb_u + B1_OFF };

    int tid  = threadIdx.x;
    int lane = tid & 31, wid = tid >> 5;
    int wm = wid >> 2, wn = wid & 3;     // 2 x 4 warp grid
    int g = lane >> 2, q = lane & 3;

    int bt = blockIdx.x;                 // (b, t)
    int b  = bt >> 8;                    // T = 256
    size_t obase = (size_t)bt * (UU * VC);
    const float* grow = g_dev + (size_t)b * UU * JH;
    const float* frow = f_dev + (size_t)bt * JH;

    // ---- prologue: bias + f into SMEM ----
    for (int i = tid; i < VP; i += 256) bias_s[i] = (i < VC) ? b_joint[i] : 0.f;
    for (int i = tid; i < JH; i += 256) f_s[i] = frow[i];
    __syncthreads();

    // ---- build A = relu(f + g) bf16 into swizzled SMEM ----
    // 128 rows x 320 bf16x2 pairs
    for (int i = tid; i < 128 * 320; i += 256) {
        int u = i / 320, p = i - u * 320;
        const float2 gv = *(const float2*)(grow + (size_t)u * JH + 2 * p);
        float h0 = fmaxf(gv.x + f_s[2*p],     0.f);
        float h1 = fmaxf(gv.y + f_s[2*p + 1], 0.f);
        uint32_t pk = pack_bf16x2(h0, h1);
        uint32_t addr = a_addr(a_base, u, p >> 2) + (p & 3) * 4;
        *(uint32_t*)(sb + (addr - sb_u)) = pk;
    }
    __syncthreads();

    // ---- main loop over 9 class chunks, 10 K-slices each ----
    float acc[4][4][4];
    float sums[4][2];
#pragma unroll
    for (int mt = 0; mt < 4; mt++) {
#pragma unroll
        for (int h = 0; h < 2; h++) sums[mt][h] = 0.f;
    }

    // issue slice (0,0)
    {
#pragma unroll
        for (int j = 0; j < 4; j++) {
            int i = tid + j * 256;
            int n = i >> 3, ch = i & 7;
            cp_async16(b_addr(b_base[0], n, ch), w_dev + (size_t)n * JH + ch * 8);
        }
        cp_commit();
    }

    for (int c = 0; c < NCHUNK; c++) {
#pragma unroll
        for (int mt = 0; mt < 4; mt++)
#pragma unroll
            for (int nt = 0; nt < 4; nt++)
#pragma unroll
                for (int k = 0; k < 4; k++) acc[mt][nt][k] = 0.f;

#pragma unroll 1
        for (int ks = 0; ks < NSLICE; ks++) {
            bool has_next = !(c == NCHUNK - 1 && ks == NSLICE - 1);
            if (has_next) {
                int nc = (ks == NSLICE - 1) ? c + 1 : c;
                int nks = (ks == NSLICE - 1) ? 0 : ks + 1;
                uint32_t dstb = b_base[(ks + 1) & 1];
                const __nv_bfloat16* src = w_dev + (size_t)nc * NC * JH + nks * 64;
#pragma unroll
                for (int j = 0; j < 4; j++) {
                    int i = tid + j * 256;
                    int n = i >> 3, ch = i & 7;
                    cp_async16(b_addr(dstb, n, ch), src + (size_t)n * JH + ch * 8);
                }
                cp_commit();
                cp_wait1();
            } else {
                cp_wait0();
            }
            __syncthreads();

            uint32_t bs = b_base[ks & 1];
#pragma unroll
            for (int kk = 0; kk < 4; kk++) {
                uint32_t afr[4][4];
                uint32_t bfr[4][2];
                int c16 = ks * 8 + kk * 2;
#pragma unroll
                for (int mt = 0; mt < 4; mt++) {
                    int row = wm * 64 + mt * 16 + (lane & 15);
                    int chk = c16 + (lane >> 4);
                    ldsm_x4(afr[mt][0], afr[mt][1], afr[mt][2], afr[mt][3],
                            a_addr(a_base, row, chk));
                }
#pragma unroll
                for (int nt = 0; nt < 4; nt++) {
                    int n = wn * 32 + nt * 8 + (lane & 7);
                    int chk = kk * 2 + ((lane >> 3) & 1);
                    ldsm_x2(bfr[nt][0], bfr[nt][1], b_addr(bs, n, chk));
                }
#pragma unroll
                for (int mt = 0; mt < 4; mt++)
#pragma unroll
                    for (int nt = 0; nt < 4; nt++)
                        mma16816(acc[mt][nt], afr[mt], bfr[nt]);
            }
            __syncthreads();
        }

        // ---- epilogue: bias add, raw logit store, register exp-sum ----
#pragma unroll
        for (int mt = 0; mt < 4; mt++) {
#pragma unroll
            for (int h = 0; h < 2; h++) {
                int u = wm * 64 + mt * 16 + h * 8 + g;
                float* rb = out + obase + (size_t)u * VC;
#pragma unroll
                for (int nt = 0; nt < 4; nt++) {
                    int v = c * NC + wn * 32 + nt * 8 + q * 2;
                    float l0 = acc[mt][nt][h*2 + 0] + bias_s[v];
                    float l1 = acc[mt][nt][h*2 + 1] + bias_s[v + 1];
                    if (v + 1 < VC) {
                        rb[v] = l0; rb[v + 1] = l1;
                        sums[mt][h] += __expf(l0) + __expf(l1);
                    } else if (v < VC) {
                        rb[v] = l0;
                        sums[mt][h] += __expf(l0);
                    }
                }
            }
        }
    }

    // ---- final per-row logsumexp ----
#pragma unroll
    for (int mt = 0; mt < 4; mt++) {
#pragma unroll
        for (int h = 0; h < 2; h++) {
            float s = sums[mt][h];
            s += __shfl_xor_sync(0xFFFFFFFF, s, 1);
            s += __shfl_xor_sync(0xFFFFFFFF, s, 2);
            if (q == 0) red[wn * 128 + wm * 64 + mt * 16 + h * 8 + g] = s;
        }
    }
    __syncthreads();
    if (tid < 128) {
        float s = red[tid] + red[128 + tid] + red[256 + tid] + red[384 + tid];
        lse_s[tid] = __logf(s);
    }
    __syncthreads();

    // ---- fixup: subtract lse (region is L2-hot) ----
    for (int u = 0; u < UU; u++) {
        float l = lse_s[u];
        float* rb = out + obase + (size_t)u * VC;
        for (int i = tid; i < VC; i += 256) rb[i] -= l;
    }
}

// ===================== launch ================================
extern "C" void kernel_launch(void* const* d_in, const int* in_sizes, int n_in,
                              void* d_out, int out_size) {
    const float* enc     = (const float*)d_in[0];
    const float* dec     = (const float*)d_in[1];
    const float* W_enc   = (const float*)d_in[2];
    const float* b_enc   = (const float*)d_in[3];
    const float* W_pred  = (const float*)d_in[4];
    const float* b_pred  = (const float*)d_in[5];
    const float* W_joint = (const float*)d_in[6];
    const float* b_joint = (const float*)d_in[7];
    float* out = (float*)d_out;

    cudaFuncSetAttribute(joint_kernel, cudaFuncAttributeMaxDynamicSharedMemorySize, DYN_SMEM);

    float *f_ptr, *g_ptr;
    cudaGetSymbolAddress((void**)&f_ptr, f_dev);
    cudaGetSymbolAddress((void**)&g_ptr, g_dev);

    wconv_kernel<<<(VP*JH + 255)/256, 256>>>(W_joint);
    proj_kernel<<<dim3(TT/32, JH/64, BB), 256>>>(enc, W_enc, b_enc, f_ptr, ENC_H, TT);
    proj_kernel<<<dim3(UU/32, JH/64, BB), 256>>>(dec, W_pred, b_pred, g_ptr, PRED_H, UU);
    joint_kernel<<<BB*TT, 256, DYN_SMEM>>>(b_joint, out);
}

// round 4
// speedup vs baseline: 1.2201x; 1.2201x over previous
#include <cuda_runtime.h>
#include <cuda_bf16.h>
#include <cstdint>
#include <math.h>

// ===================== problem constants =====================
#define BB 4
#define TT 256
#define UU 128
#define ENC_H 512
#define PRED_H 640
#define JH 640
#define VC 1025            // real classes
#define VP 1152            // padded classes (9 * 128)
#define NCHUNK 9
#define NC 128             // classes per chunk
#define NSLICE 10          // K slices of 64 per chunk
#define NSL_TOT 90         // total slices
#define NTHREADS 512

// ===================== device scratch ========================
__device__ float f_dev[BB*TT*JH];
__device__ float g_dev[BB*UU*JH];
__device__ __nv_bfloat16 w_dev[VP*JH];

// ===================== helpers ===========================
__device__ __forceinline__ uint32_t smem_to_u32(const void* p) {
    uint32_t a;
    asm("{ .reg .u64 t; cvta.to.shared.u64 t, %1; cvt.u32.u64 %0, t; }" : "=r"(a) : "l"(p));
    return a;
}
__device__ __forceinline__ uint32_t pack_bf16x2(float lo, float hi) {
    uint32_t p;
    asm("cvt.rn.bf16x2.f32 %0, %1, %2;" : "=r"(p) : "f"(hi), "f"(lo));
    return p;
}
__device__ __forceinline__ void ldsm_x4(uint32_t& r0, uint32_t& r1, uint32_t& r2, uint32_t& r3, uint32_t addr) {
    asm volatile("ldmatrix.sync.aligned.m8n8.x4.shared.b16 {%0,%1,%2,%3}, [%4];"
        : "=r"(r0), "=r"(r1), "=r"(r2), "=r"(r3) : "r"(addr));
}
__device__ __forceinline__ void mma16816(float* d, const uint32_t* a, const uint32_t* b) {
    asm volatile("mma.sync.aligned.m16n8k16.row.col.f32.bf16.bf16.f32 "
        "{%0,%1,%2,%3}, {%4,%5,%6,%7}, {%8,%9}, {%0,%1,%2,%3};"
        : "+f"(d[0]), "+f"(d[1]), "+f"(d[2]), "+f"(d[3])
        : "r"(a[0]), "r"(a[1]), "r"(a[2]), "r"(a[3]), "r"(b[0]), "r"(b[1]));
}
__device__ __forceinline__ void cp_async16(uint32_t saddr, const void* gaddr) {
    asm volatile("cp.async.cg.shared.global [%0], [%1], 16;" :: "r"(saddr), "l"(gaddr));
}
__device__ __forceinline__ void cp_commit() { asm volatile("cp.async.commit_group;"); }
__device__ __forceinline__ void cp_wait1() { asm volatile("cp.async.wait_group 1;"); }

// SMEM swizzled addressing (16B chunk granularity, XOR row&7)
__device__ __forceinline__ uint32_t a_addr(uint32_t base, int row, int chunk) {
    int sc = (chunk & ~7) | ((chunk & 7) ^ (row & 7));
    return base + (uint32_t)(row * 1280 + sc * 16);
}
__device__ __forceinline__ uint32_t b_addr(uint32_t base, int n, int chunk) {
    return base + (uint32_t)(n * 128 + ((chunk ^ n) & 7) * 16);
}

// ===================== SMEM layout (relative to 1KB-aligned base) ==========
#define A_OFF      0                   // 128 x 640 bf16 swizzled: 163840 B
#define B_OFF      163840              // 3 x (128 x 64 bf16) = 49152 B
#define BIAS_OFF   212992              // 1152 fp32
#define F_OFF      217600              // 640 fp32
#define RED_OFF    220160              // 4 x 128 fp32
#define LSE_OFF    222208              // 128 fp32
#define SMEM_USED  222720
#define DYN_SMEM   (SMEM_USED + 1024)

// ===================== small projection GEMM (f and g) ======================
__global__ void proj_kernel(const float* __restrict__ X, const float* __restrict__ W,
                            const float* __restrict__ bias, float* __restrict__ Out,
                            int H, int R) {
    __shared__ float Xs[32*33];
    __shared__ float Ws[32*65];
    int r0 = blockIdx.x * 32, j0 = blockIdx.y * 64, b = blockIdx.z;
    int tid = threadIdx.x;
    int r = tid & 31, jg = tid >> 5;
    float acc[8];
#pragma unroll
    for (int i = 0; i < 8; i++) acc[i] = 0.f;
    const float* Xb = X + (size_t)b * H * R;
    for (int h0 = 0; h0 < H; h0 += 32) {
        for (int i = tid; i < 32*32; i += 256) {
            int hh = i >> 5, rr = i & 31;
            Xs[hh*33 + rr] = Xb[(size_t)(h0 + hh) * R + r0 + rr];
        }
        for (int i = tid; i < 64*32; i += 256) {
            int jj = i >> 5, hh = i & 31;
            Ws[hh*65 + jj] = W[(size_t)(j0 + jj) * H + h0 + hh];
        }
        __syncthreads();
#pragma unroll
        for (int hh = 0; hh < 32; hh++) {
            float x = Xs[hh*33 + r];
#pragma unroll
            for (int jj = 0; jj < 8; jj++)
                acc[jj] = fmaf(x, Ws[hh*65 + jg*8 + jj], acc[jj]);
        }
        __syncthreads();
    }
    float* o = Out + ((size_t)b * R + r0 + r) * JH + j0 + jg*8;
#pragma unroll
    for (int jj = 0; jj < 8; jj++) o[jj] = acc[jj] + bias[j0 + jg*8 + jj];
}

// ===================== W_joint fp32 -> bf16 (padded) ========================
__global__ void wconv_kernel(const float* __restrict__ Wj) {
    int idx = blockIdx.x * 256 + threadIdx.x;
    if (idx >= VP * JH) return;
    float v = (idx < VC * JH) ? Wj[idx] : 0.f;
    w_dev[idx] = __float2bfloat16(v);
}

// ===================== slice loader (cp.async) ==============================
__device__ __forceinline__ void load_slice(uint32_t buf, int slice, int tid) {
    int c = slice / NSLICE, ks = slice - c * NSLICE;
    const __nv_bfloat16* src = w_dev + (size_t)c * NC * JH + ks * 64;
#pragma unroll
    for (int j = 0; j < 2; j++) {
        int i = tid + j * NTHREADS;
        int n = i >> 3, ch = i & 7;
        cp_async16(b_addr(buf, n, ch), src + (size_t)n * JH + ch * 8);
    }
}

// ===================== fused joint GEMM + log_softmax ======================
__global__ void __launch_bounds__(NTHREADS, 1)
joint_kernel(const float* __restrict__ b_joint, float* __restrict__ out) {
    extern __shared__ char smraw[];
    uint32_t sm_u = smem_to_u32(smraw);
    uint32_t pad = ((sm_u + 1023) & ~1023u) - sm_u;
    char* sb = smraw + pad;
    uint32_t sb_u = sm_u + pad;

    float* bias_s = (float*)(sb + BIAS_OFF);
    float* f_s    = (float*)(sb + F_OFF);
    float* red    = (float*)(sb + RED_OFF);
    float* lse_s  = (float*)(sb + LSE_OFF);
    uint32_t a_base = sb_u + A_OFF;
    uint32_t b_base[3] = { sb_u + B_OFF, sb_u + B_OFF + 16384, sb_u + B_OFF + 32768 };

    int tid  = threadIdx.x;
    int lane = tid & 31, wid = tid >> 5;
    int wm = wid >> 2, wn = wid & 3;     // 4 x 4 warp grid
    int g = lane >> 2, q = lane & 3;

    int bt = blockIdx.x;                 // (b, t)
    int b  = bt >> 8;                    // T = 256
    size_t obase = (size_t)bt * (UU * VC);
    const float* grow = g_dev + (size_t)b * UU * JH;
    const float* frow = f_dev + (size_t)bt * JH;

    // ---- prologue: kick off first two B slices, load bias + f ----
    load_slice(b_base[0], 0, tid); cp_commit();
    load_slice(b_base[1], 1, tid); cp_commit();
    for (int i = tid; i < VP; i += NTHREADS) bias_s[i] = (i < VC) ? b_joint[i] : 0.f;
    for (int i = tid; i < JH; i += NTHREADS) f_s[i] = frow[i];
    __syncthreads();

    // ---- build A = relu(f + g) bf16 into swizzled SMEM ----
    for (int i = tid; i < 128 * 320; i += NTHREADS) {
        int u = i / 320, p = i - u * 320;
        const float2 gv = *(const float2*)(grow + (size_t)u * JH + 2 * p);
        float h0 = fmaxf(gv.x + f_s[2*p],     0.f);
        float h1 = fmaxf(gv.y + f_s[2*p + 1], 0.f);
        uint32_t pk = pack_bf16x2(h0, h1);
        uint32_t addr = a_addr(a_base, u, p >> 2) + (p & 3) * 4;
        *(uint32_t*)(sb + (addr - sb_u)) = pk;
    }
    cp_wait1();        // stage 0 landed (stage 1 may still fly)
    __syncthreads();   // publish stage 0 + A to all warps

    // ---- main loop: 9 class chunks x 10 K-slices, 3-stage pipeline ----
    float acc[2][4][4];
    float sums[2][2];
#pragma unroll
    for (int mt = 0; mt < 2; mt++)
#pragma unroll
        for (int h = 0; h < 2; h++) sums[mt][h] = 0.f;

    for (int c = 0; c < NCHUNK; c++) {
#pragma unroll
        for (int mt = 0; mt < 2; mt++)
#pragma unroll
            for (int nt = 0; nt < 4; nt++)
#pragma unroll
                for (int k = 0; k < 4; k++) acc[mt][nt][k] = 0.f;

#pragma unroll 1
        for (int ks = 0; ks < NSLICE; ks++) {
            int i = c * NSLICE + ks;
            int nxt = i + 2;
            if (nxt < NSL_TOT) load_slice(b_base[nxt % 3], nxt, tid);
            cp_commit();

            uint32_t bs = b_base[i % 3];
#pragma unroll
            for (int kk = 0; kk < 4; kk++) {
                uint32_t afr[2][4];
                uint32_t bfr[4][2];
                int c16 = ks * 8 + kk * 2;
#pragma unroll
                for (int mt = 0; mt < 2; mt++) {
                    int row = wm * 32 + mt * 16 + (lane & 15);
                    int chk = c16 + (lane >> 4);
                    ldsm_x4(afr[mt][0], afr[mt][1], afr[mt][2], afr[mt][3],
                            a_addr(a_base, row, chk));
                }
#pragma unroll
                for (int pr = 0; pr < 2; pr++) {
                    int m = lane >> 3;
                    int n = wn * 32 + pr * 16 + ((m >> 1) << 3) + (lane & 7);
                    int chk = kk * 2 + (m & 1);
                    ldsm_x4(bfr[pr*2][0], bfr[pr*2][1], bfr[pr*2+1][0], bfr[pr*2+1][1],
                            b_addr(bs, n, chk));
                }
#pragma unroll
                for (int mt = 0; mt < 2; mt++)
#pragma unroll
                    for (int nt = 0; nt < 4; nt++)
                        mma16816(acc[mt][nt], afr[mt], bfr[nt]);
            }
            cp_wait1();        // stage i+1 landed (FIFO completion)
            __syncthreads();   // publish stage i+1; all warps done with stage i
        }

        // ---- epilogue: bias add, raw logit store, register exp-sum ----
        // (overlaps with the 2 in-flight cp.async loads of the next chunk)
#pragma unroll
        for (int mt = 0; mt < 2; mt++) {
#pragma unroll
            for (int h = 0; h < 2; h++) {
                int u = wm * 32 + mt * 16 + h * 8 + g;
                float* rb = out + obase + (size_t)u * VC;
#pragma unroll
                for (int nt = 0; nt < 4; nt++) {
                    int v = c * NC + wn * 32 + nt * 8 + q * 2;
                    float l0 = acc[mt][nt][h*2 + 0] + bias_s[v];
                    float l1 = acc[mt][nt][h*2 + 1] + bias_s[v + 1];
                    if (v + 1 < VC) {
                        rb[v] = l0; rb[v + 1] = l1;
                        sums[mt][h] += __expf(l0) + __expf(l1);
                    } else if (v < VC) {
                        rb[v] = l0;
                        sums[mt][h] += __expf(l0);
                    }
                }
            }
        }
    }

    // ---- final per-row logsumexp ----
#pragma unroll
    for (int mt = 0; mt < 2; mt++) {
#pragma unroll
        for (int h = 0; h < 2; h++) {
            float s = sums[mt][h];
            s += __shfl_xor_sync(0xFFFFFFFF, s, 1);
            s += __shfl_xor_sync(0xFFFFFFFF, s, 2);
            if (q == 0) red[wn * 128 + wm * 32 + mt * 16 + h * 8 + g] = s;
        }
    }
    __syncthreads();
    if (tid < 128) {
        float s = red[tid] + red[128 + tid] + red[256 + tid] + red[384 + tid];
        lse_s[tid] = __logf(s);
    }
    __syncthreads();

    // ---- fixup: subtract lse (region is L2-hot) ----
    for (int u = 0; u < UU; u++) {
        float l = lse_s[u];
        float* rb = out + obase + (size_t)u * VC;
        for (int i = tid; i < VC; i += NTHREADS) rb[i] -= l;
    }
}

// ===================== launch ================================
extern "C" void kernel_launch(void* const* d_in, const int* in_sizes, int n_in,
                              void* d_out, int out_size) {
    const float* enc     = (const float*)d_in[0];
    const float* dec     = (const float*)d_in[1];
    const float* W_enc   = (const float*)d_in[2];
    const float* b_enc   = (const float*)d_in[3];
    const float* W_pred  = (const float*)d_in[4];
    const float* b_pred  = (const float*)d_in[5];
    const float* W_joint = (const float*)d_in[6];
    const float* b_joint = (const float*)d_in[7];
    float* out = (float*)d_out;

    cudaFuncSetAttribute(joint_kernel, cudaFuncAttributeMaxDynamicSharedMemorySize, DYN_SMEM);

    float *f_ptr, *g_ptr;
    cudaGetSymbolAddress((void**)&f_ptr, f_dev);
    cudaGetSymbolAddress((void**)&g_ptr, g_dev);

    wconv_kernel<<<(VP*JH + 255)/256, 256>>>(W_joint);
    proj_kernel<<<dim3(TT/32, JH/64, BB), 256>>>(enc, W_enc, b_enc, f_ptr, ENC_H, TT);
    proj_kernel<<<dim3(UU/32, JH/64, BB), 256>>>(dec, W_pred, b_pred, g_ptr, PRED_H, UU);
    joint_kernel<<<BB*TT, NTHREADS, DYN_SMEM>>>(b_joint, out);
}

// round 5
// speedup vs baseline: 1.2210x; 1.0007x over previous
#include <cuda_runtime.h>
#include <cuda_bf16.h>
#include <cstdint>
#include <math.h>

// ===================== problem constants =====================
#define BB 4
#define TT 256
#define UU 128
#define ENC_H 512
#define PRED_H 640
#define JH 640
#define VC 1025            // real classes
#define VP 1152            // padded classes (9 * 128)
#define NCHUNK 9
#define NC 128             // classes per chunk
#define NSLICE 10          // K slices of 64 per chunk
#define NSL_TOT 90         // total slices
#define NTHREADS 512

// ===================== device scratch ========================
__device__ float f_dev[BB*TT*JH];
__device__ float g_dev[BB*UU*JH];
__device__ __nv_bfloat16 w_dev[VP*JH];

// ===================== helpers ===========================
__device__ __forceinline__ uint32_t smem_to_u32(const void* p) {
    uint32_t a;
    asm("{ .reg .u64 t; cvta.to.shared.u64 t, %1; cvt.u32.u64 %0, t; }" : "=r"(a) : "l"(p));
    return a;
}
__device__ __forceinline__ uint32_t pack_bf16x2(float lo, float hi) {
    uint32_t p;
    asm("cvt.rn.bf16x2.f32 %0, %1, %2;" : "=r"(p) : "f"(hi), "f"(lo));
    return p;
}
__device__ __forceinline__ void ldsm_x4(uint32_t& r0, uint32_t& r1, uint32_t& r2, uint32_t& r3, uint32_t addr) {
    asm volatile("ldmatrix.sync.aligned.m8n8.x4.shared.b16 {%0,%1,%2,%3}, [%4];"
        : "=r"(r0), "=r"(r1), "=r"(r2), "=r"(r3) : "r"(addr));
}
__device__ __forceinline__ void mma16816(float* d, const uint32_t* a, const uint32_t* b) {
    asm volatile("mma.sync.aligned.m16n8k16.row.col.f32.bf16.bf16.f32 "
        "{%0,%1,%2,%3}, {%4,%5,%6,%7}, {%8,%9}, {%0,%1,%2,%3};"
        : "+f"(d[0]), "+f"(d[1]), "+f"(d[2]), "+f"(d[3])
        : "r"(a[0]), "r"(a[1]), "r"(a[2]), "r"(a[3]), "r"(b[0]), "r"(b[1]));
}
__device__ __forceinline__ void cp_async16(uint32_t saddr, const void* gaddr) {
    asm volatile("cp.async.cg.shared.global [%0], [%1], 16;" :: "r"(saddr), "l"(gaddr));
}
__device__ __forceinline__ void cp_commit() { asm volatile("cp.async.commit_group;"); }
__device__ __forceinline__ void cp_wait1() { asm volatile("cp.async.wait_group 1;"); }

// SMEM swizzled addressing (16B chunk granularity, XOR row&7) — used in
// prologue / loader only; the MMA loop uses precomputed offsets.
__device__ __forceinline__ uint32_t a_addr(uint32_t base, int row, int chunk) {
    int sc = (chunk & ~7) | ((chunk & 7) ^ (row & 7));
    return base + (uint32_t)(row * 1280 + sc * 16);
}
__device__ __forceinline__ uint32_t b_addr(uint32_t base, int n, int chunk) {
    return base + (uint32_t)(n * 128 + ((chunk ^ n) & 7) * 16);
}

// ===================== SMEM layout (relative to 1KB-aligned base) ==========
#define A_OFF      0                   // 128 x 640 bf16 swizzled: 163840 B
#define B_OFF      163840              // 3 x (128 x 64 bf16) = 49152 B
#define BIAS_OFF   212992              // 1152 fp32
#define F_OFF      217600              // 640 fp32
#define RED_OFF    220160              // 4 x 128 fp32
#define LSE_OFF    222208              // 128 fp32
#define SMEM_USED  222720
#define DYN_SMEM   (SMEM_USED + 1024)

// ===================== small projection GEMM (f and g) ======================
__global__ void proj_kernel(const float* __restrict__ X, const float* __restrict__ W,
                            const float* __restrict__ bias, float* __restrict__ Out,
                            int H, int R) {
    __shared__ float Xs[32*33];
    __shared__ float Ws[32*65];
    int r0 = blockIdx.x * 32, j0 = blockIdx.y * 64, b = blockIdx.z;
    int tid = threadIdx.x;
    int r = tid & 31, jg = tid >> 5;
    float acc[8];
#pragma unroll
    for (int i = 0; i < 8; i++) acc[i] = 0.f;
    const float* Xb = X + (size_t)b * H * R;
    for (int h0 = 0; h0 < H; h0 += 32) {
        for (int i = tid; i < 32*32; i += 256) {
            int hh = i >> 5, rr = i & 31;
            Xs[hh*33 + rr] = Xb[(size_t)(h0 + hh) * R + r0 + rr];
        }
        for (int i = tid; i < 64*32; i += 256) {
            int jj = i >> 5, hh = i & 31;
            Ws[hh*65 + jj] = W[(size_t)(j0 + jj) * H + h0 + hh];
        }
        __syncthreads();
#pragma unroll
        for (int hh = 0; hh < 32; hh++) {
            float x = Xs[hh*33 + r];
#pragma unroll
            for (int jj = 0; jj < 8; jj++)
                acc[jj] = fmaf(x, Ws[hh*65 + jg*8 + jj], acc[jj]);
        }
        __syncthreads();
    }
    float* o = Out + ((size_t)b * R + r0 + r) * JH + j0 + jg*8;
#pragma unroll
    for (int jj = 0; jj < 8; jj++) o[jj] = acc[jj] + bias[j0 + jg*8 + jj];
}

// ===================== W_joint fp32 -> bf16 (padded) ========================
__global__ void wconv_kernel(const float* __restrict__ Wj) {
    int idx = blockIdx.x * 256 + threadIdx.x;
    if (idx >= VP * JH) return;
    float v = (idx < VC * JH) ? Wj[idx] : 0.f;
    w_dev[idx] = __float2bfloat16(v);
}

// ===================== slice loader (cp.async) ==============================
__device__ __forceinline__ void load_slice(uint32_t buf, int slice, int tid) {
    int c = slice / NSLICE, ks = slice - c * NSLICE;
    const __nv_bfloat16* src = w_dev + (size_t)c * NC * JH + ks * 64;
#pragma unroll
    for (int j = 0; j < 2; j++) {
        int i = tid + j * NTHREADS;
        int n = i >> 3, ch = i & 7;
        cp_async16(b_addr(buf, n, ch), src + (size_t)n * JH + ch * 8);
    }
}

// ===================== fragment loader (precomputed offsets) ================
__device__ __forceinline__ void load_frags(uint32_t aslice, uint32_t bs,
                                           const uint32_t* pA, const uint32_t* qB, int kk,
                                           uint32_t afr[2][4], uint32_t bfr[4][2]) {
    ldsm_x4(afr[0][0], afr[0][1], afr[0][2], afr[0][3], aslice + pA[0*4 + kk]);
    ldsm_x4(afr[1][0], afr[1][1], afr[1][2], afr[1][3], aslice + pA[1*4 + kk]);
    ldsm_x4(bfr[0][0], bfr[0][1], bfr[1][0], bfr[1][1], bs + qB[0*4 + kk]);
    ldsm_x4(bfr[2][0], bfr[2][1], bfr[3][0], bfr[3][1], bs + qB[1*4 + kk]);
}

// ===================== fused joint GEMM + log_softmax ======================
__global__ void __launch_bounds__(NTHREADS, 1)
joint_kernel(const float* __restrict__ b_joint, float* __restrict__ out) {
    extern __shared__ char smraw[];
    uint32_t sm_u = smem_to_u32(smraw);
    uint32_t pad = ((sm_u + 1023) & ~1023u) - sm_u;
    char* sb = smraw + pad;
    uint32_t sb_u = sm_u + pad;

    float* bias_s = (float*)(sb + BIAS_OFF);
    float* f_s    = (float*)(sb + F_OFF);
    float* red    = (float*)(sb + RED_OFF);
    float* lse_s  = (float*)(sb + LSE_OFF);
    uint32_t a_base = sb_u + A_OFF;
    uint32_t b_base[3] = { sb_u + B_OFF, sb_u + B_OFF + 16384, sb_u + B_OFF + 32768 };

    int tid  = threadIdx.x;
    int lane = tid & 31, wid = tid >> 5;
    int wm = wid >> 2, wn = wid & 3;     // 4 x 4 warp grid
    int g = lane >> 2, q = lane & 3;

    int bt = blockIdx.x;                 // (b, t)
    int b  = bt >> 8;                    // T = 256
    size_t obase = (size_t)bt * (UU * VC);
    const float* grow = g_dev + (size_t)b * UU * JH;
    const float* frow = f_dev + (size_t)bt * JH;

    // ---- precompute swizzled ldmatrix offsets (invariant per warp/lane) ----
    uint32_t pA[8], qB[8];
    {
        int hl = lane >> 4;
#pragma unroll
        for (int mt = 0; mt < 2; mt++) {
            int row = wm * 32 + mt * 16 + (lane & 15);
#pragma unroll
            for (int kk = 0; kk < 4; kk++)
                pA[mt*4 + kk] = (uint32_t)(row * 1280 + (((kk*2 + hl) ^ (row & 7)) << 4));
        }
        int m = lane >> 3;
#pragma unroll
        for (int pr = 0; pr < 2; pr++) {
            int n = wn * 32 + pr * 16 + ((m >> 1) << 3) + (lane & 7);
#pragma unroll
            for (int kk = 0; kk < 4; kk++)
                qB[pr*4 + kk] = (uint32_t)(n * 128 + ((((kk*2 + (m & 1)) ^ n) & 7) << 4));
        }
    }

    // ---- prologue: kick off first two B slices, load bias + f ----
    load_slice(b_base[0], 0, tid); cp_commit();
    load_slice(b_base[1], 1, tid); cp_commit();
    for (int i = tid; i < VP; i += NTHREADS) bias_s[i] = (i < VC) ? b_joint[i] : 0.f;
    for (int i = tid; i < JH; i += NTHREADS) f_s[i] = frow[i];
    __syncthreads();

    // ---- build A = relu(f + g) bf16 into swizzled SMEM ----
    for (int i = tid; i < 128 * 320; i += NTHREADS) {
        int u = i / 320, p = i - u * 320;
        const float2 gv = *(const float2*)(grow + (size_t)u * JH + 2 * p);
        float h0 = fmaxf(gv.x + f_s[2*p],     0.f);
        float h1 = fmaxf(gv.y + f_s[2*p + 1], 0.f);
        uint32_t pk = pack_bf16x2(h0, h1);
        uint32_t addr = a_addr(a_base, u, p >> 2) + (p & 3) * 4;
        *(uint32_t*)(sb + (addr - sb_u)) = pk;
    }
    cp_wait1();        // stage 0 landed (stage 1 may still fly)
    __syncthreads();   // publish stage 0 + A to all warps

    // ---- main loop: 9 chunks x 10 K-slices, 3-stage cp.async pipeline ----
    float acc[2][4][4];
    float sums[2][2];
#pragma unroll
    for (int mt = 0; mt < 2; mt++)
#pragma unroll
        for (int h = 0; h < 2; h++) sums[mt][h] = 0.f;

    for (int c = 0; c < NCHUNK; c++) {
#pragma unroll
        for (int mt = 0; mt < 2; mt++)
#pragma unroll
            for (int nt = 0; nt < 4; nt++)
#pragma unroll
                for (int k = 0; k < 4; k++) acc[mt][nt][k] = 0.f;

#pragma unroll 1
        for (int ks = 0; ks < NSLICE; ks++) {
            int i = c * NSLICE + ks;
            int nxt = i + 2;
            // issue next-next slice FIRST so GMEM latency hides under MMAs
            if (nxt < NSL_TOT) load_slice(b_base[nxt % 3], nxt, tid);
            cp_commit();

            uint32_t aslice = a_base + (uint32_t)(ks * 128);
            uint32_t bs = b_base[i % 3];

            // register double-buffered kk pipeline
            uint32_t afr[2][2][4], bfr[2][4][2];
            load_frags(aslice, bs, pA, qB, 0, afr[0], bfr[0]);
#pragma unroll
            for (int kk = 0; kk < 4; kk++) {
                int cur = kk & 1;
                if (kk < 3)
                    load_frags(aslice, bs, pA, qB, kk + 1, afr[cur ^ 1], bfr[cur ^ 1]);
#pragma unroll
                for (int mt = 0; mt < 2; mt++)
#pragma unroll
                    for (int nt = 0; nt < 4; nt++)
                        mma16816(acc[mt][nt], afr[cur][mt], bfr[cur][nt]);
            }
            cp_wait1();        // stage i+1 landed (FIFO completion)
            __syncthreads();   // publish stage i+1; all warps done with stage i
        }

        // ---- epilogue: bias add, raw logit store, register exp-sum ----
#pragma unroll
        for (int mt = 0; mt < 2; mt++) {
#pragma unroll
            for (int h = 0; h < 2; h++) {
                int u = wm * 32 + mt * 16 + h * 8 + g;
                float* rb = out + obase + (size_t)u * VC;
#pragma unroll
                for (int nt = 0; nt < 4; nt++) {
                    int v = c * NC + wn * 32 + nt * 8 + q * 2;
                    float l0 = acc[mt][nt][h*2 + 0] + bias_s[v];
                    float l1 = acc[mt][nt][h*2 + 1] + bias_s[v + 1];
                    if (v + 1 < VC) {
                        rb[v] = l0; rb[v + 1] = l1;
                        sums[mt][h] += __expf(l0) + __expf(l1);
                    } else if (v < VC) {
                        rb[v] = l0;
                        sums[mt][h] += __expf(l0);
                    }
                }
            }
        }
    }

    // ---- final per-row logsumexp ----
#pragma unroll
    for (int mt = 0; mt < 2; mt++) {
#pragma unroll
        for (int h = 0; h < 2; h++) {
            float s = sums[mt][h];
            s += __shfl_xor_sync(0xFFFFFFFF, s, 1);
            s += __shfl_xor_sync(0xFFFFFFFF, s, 2);
            if (q == 0) red[wn * 128 + wm * 32 + mt * 16 + h * 8 + g] = s;
        }
    }
    __syncthreads();
    if (tid < 128) {
        float s = red[tid] + red[128 + tid] + red[256 + tid] + red[384 + tid];
        lse_s[tid] = __logf(s);
    }
    __syncthreads();

    // ---- fixup: subtract lse (region is L2-hot) ----
    for (int u = 0; u < UU; u++) {
        float l = lse_s[u];
        float* rb = out + obase + (size_t)u * VC;
        for (int i = tid; i < VC; i += NTHREADS) rb[i] -= l;
    }
}

// ===================== launch ================================
extern "C" void kernel_launch(void* const* d_in, const int* in_sizes, int n_in,
                              void* d_out, int out_size) {
    const float* enc     = (const float*)d_in[0];
    const float* dec     = (const float*)d_in[1];
    const float* W_enc   = (const float*)d_in[2];
    const float* b_enc   = (const float*)d_in[3];
    const float* W_pred  = (const float*)d_in[4];
    const float* b_pred  = (const float*)d_in[5];
    const float* W_joint = (const float*)d_in[6];
    const float* b_joint = (const float*)d_in[7];
    float* out = (float*)d_out;

    cudaFuncSetAttribute(joint_kernel, cudaFuncAttributeMaxDynamicSharedMemorySize, DYN_SMEM);

    float *f_ptr, *g_ptr;
    cudaGetSymbolAddress((void**)&f_ptr, f_dev);
    cudaGetSymbolAddress((void**)&g_ptr, g_dev);

    wconv_kernel<<<(VP*JH + 255)/256, 256>>>(W_joint);
    proj_kernel<<<dim3(TT/32, JH/64, BB), 256>>>(enc, W_enc, b_enc, f_ptr, ENC_H, TT);
    proj_kernel<<<dim3(UU/32, JH/64, BB), 256>>>(dec, W_pred, b_pred, g_ptr, PRED_H, UU);
    joint_kernel<<<BB*TT, NTHREADS, DYN_SMEM>>>(b_joint, out);
}

// round 6
// speedup vs baseline: 1.4658x; 1.2005x over previous
#include <cuda_runtime.h>
#include <cuda_bf16.h>
#include <cstdint>
#include <math.h>

// ===================== problem constants =====================
#define BB 4
#define TT 256
#define UU 128
#define ENC_H 512
#define PRED_H 640
#define JH 640
#define VC 1025            // real classes
#define VP 1152            // padded classes (9 * 128)
#define NCHUNK 9
#define NC 128             // classes per chunk
#define NSLICE 10          // K slices of 64 per chunk
#define NSL_TOT 90         // total slices
#define NTHREADS 512
#define WFRAG_U32 (NSL_TOT*16*2*32*4)   // 368640 uint32 = 1.47 MB

// ===================== device scratch ========================
__device__ float f_dev[BB*TT*JH];
__device__ float g_dev[BB*UU*JH];
__device__ uint32_t wfrag_dev[WFRAG_U32];   // W_joint in MMA-fragment order

// ===================== helpers ===========================
__device__ __forceinline__ uint32_t smem_to_u32(const void* p) {
    uint32_t a;
    asm("{ .reg .u64 t; cvta.to.shared.u64 t, %1; cvt.u32.u64 %0, t; }" : "=r"(a) : "l"(p));
    return a;
}
__device__ __forceinline__ uint32_t pack_bf16x2(float lo, float hi) {
    uint32_t p;
    asm("cvt.rn.bf16x2.f32 %0, %1, %2;" : "=r"(p) : "f"(hi), "f"(lo));
    return p;
}
__device__ __forceinline__ void ldsm_x4(uint32_t& r0, uint32_t& r1, uint32_t& r2, uint32_t& r3, uint32_t addr) {
    asm volatile("ldmatrix.sync.aligned.m8n8.x4.shared.b16 {%0,%1,%2,%3}, [%4];"
        : "=r"(r0), "=r"(r1), "=r"(r2), "=r"(r3) : "r"(addr));
}
__device__ __forceinline__ void mma16816(float* d, const uint32_t* a, uint32_t b0, uint32_t b1) {
    asm volatile("mma.sync.aligned.m16n8k16.row.col.f32.bf16.bf16.f32 "
        "{%0,%1,%2,%3}, {%4,%5,%6,%7}, {%8,%9}, {%0,%1,%2,%3};"
        : "+f"(d[0]), "+f"(d[1]), "+f"(d[2]), "+f"(d[3])
        : "r"(a[0]), "r"(a[1]), "r"(a[2]), "r"(a[3]), "r"(b0), "r"(b1));
}

// SMEM swizzled addressing for A (16B chunk granularity, XOR row&7)
__device__ __forceinline__ uint32_t a_addr(uint32_t base, int row, int chunk) {
    int sc = (chunk & ~7) | ((chunk & 7) ^ (row & 7));
    return base + (uint32_t)(row * 1280 + sc * 16);
}

// ===================== SMEM layout (relative to 1KB-aligned base) ==========
#define A_OFF      0                   // 128 x 640 bf16 swizzled: 163840 B
#define BIAS_OFF   163840              // 1152 fp32
#define F_OFF      168448              // 640 fp32
#define RED_OFF    171008              // 4 x 128 fp32
#define LSE_OFF    173056              // 128 fp32
#define SMEM_USED  173568
#define DYN_SMEM   (SMEM_USED + 1024)

// ===================== small projection GEMM (f and g) ======================
__global__ void proj_kernel(const float* __restrict__ X, const float* __restrict__ W,
                            const float* __restrict__ bias, float* __restrict__ Out,
                            int H, int R) {
    __shared__ float Xs[32*33];
    __shared__ float Ws[32*65];
    int r0 = blockIdx.x * 32, j0 = blockIdx.y * 64, b = blockIdx.z;
    int tid = threadIdx.x;
    int r = tid & 31, jg = tid >> 5;
    float acc[8];
#pragma unroll
    for (int i = 0; i < 8; i++) acc[i] = 0.f;
    const float* Xb = X + (size_t)b * H * R;
    for (int h0 = 0; h0 < H; h0 += 32) {
        for (int i = tid; i < 32*32; i += 256) {
            int hh = i >> 5, rr = i & 31;
            Xs[hh*33 + rr] = Xb[(size_t)(h0 + hh) * R + r0 + rr];
        }
        for (int i = tid; i < 64*32; i += 256) {
            int jj = i >> 5, hh = i & 31;
            Ws[hh*65 + jj] = W[(size_t)(j0 + jj) * H + h0 + hh];
        }
        __syncthreads();
#pragma unroll
        for (int hh = 0; hh < 32; hh++) {
            float x = Xs[hh*33 + r];
#pragma unroll
            for (int jj = 0; jj < 8; jj++)
                acc[jj] = fmaf(x, Ws[hh*65 + jg*8 + jj], acc[jj]);
        }
        __syncthreads();
    }
    float* o = Out + ((size_t)b * R + r0 + r) * JH + j0 + jg*8;
#pragma unroll
    for (int jj = 0; jj < 8; jj++) o[jj] = acc[jj] + bias[j0 + jg*8 + jj];
}

// ===================== W_joint fp32 -> bf16 fragment order ==================
// Layout (uint4 granularity): u4_index = ((s*16 + j)*2 + h)*32 + lane
//   s = slice (c*10+ks), j = n-octet within padded vocab chunk (0..15),
//   h = kk-half (0: kk0/1, 1: kk2/3), lane = thread in warp.
// Component q of the uint4 = bf16x2 {B[v][k], B[v][k+1]} with
//   v = c*128 + j*8 + (lane>>2)
//   k = ks*64 + (h*2 + (q>>1))*16 + (q&1)*8 + (lane&3)*2
__global__ void wconv_kernel(const float* __restrict__ Wj) {
    int i = blockIdx.x * 256 + threadIdx.x;
    if (i >= WFRAG_U32) return;
    int q   = i & 3;
    int u4  = i >> 2;
    int T   = u4 & 31;
    int rest = u4 >> 5;
    int h = rest & 1; rest >>= 1;
    int j = rest & 15;
    int s = rest >> 4;
    int c = s / 10, ks = s - c * 10;
    int v = c * 128 + j * 8 + (T >> 2);
    int k = ks * 64 + (h * 2 + (q >> 1)) * 16 + (q & 1) * 8 + (T & 3) * 2;
    float v0 = 0.f, v1 = 0.f;
    if (v < VC) {
        v0 = Wj[(size_t)v * JH + k];
        v1 = Wj[(size_t)v * JH + k + 1];
    }
    wfrag_dev[i] = pack_bf16x2(v0, v1);
}

// ===================== fused joint GEMM + log_softmax ======================
__global__ void __launch_bounds__(NTHREADS, 1)
joint_kernel(const float* __restrict__ b_joint, float* __restrict__ out) {
    extern __shared__ char smraw[];
    uint32_t sm_u = smem_to_u32(smraw);
    uint32_t pad = ((sm_u + 1023) & ~1023u) - sm_u;
    char* sb = smraw + pad;
    uint32_t sb_u = sm_u + pad;

    float* bias_s = (float*)(sb + BIAS_OFF);
    float* f_s    = (float*)(sb + F_OFF);
    float* red    = (float*)(sb + RED_OFF);
    float* lse_s  = (float*)(sb + LSE_OFF);
    uint32_t a_base = sb_u + A_OFF;

    int tid  = threadIdx.x;
    int lane = tid & 31, wid = tid >> 5;
    int wm = wid >> 2, wn = wid & 3;     // 4 x 4 warp grid
    int g = lane >> 2, q = lane & 3;

    int bt = blockIdx.x;                 // (b, t)
    int b  = bt >> 8;                    // T = 256
    size_t obase = (size_t)bt * (UU * VC);
    const float* grow = g_dev + (size_t)b * UU * JH;
    const float* frow = f_dev + (size_t)bt * JH;

    // ---- precompute swizzled A ldmatrix offsets (invariant per warp/lane) ----
    uint32_t pA[8];
    {
        int hl = lane >> 4;
#pragma unroll
        for (int mt = 0; mt < 2; mt++) {
            int row = wm * 32 + mt * 16 + (lane & 15);
#pragma unroll
            for (int kk = 0; kk < 4; kk++)
                pA[mt*4 + kk] = (uint32_t)(row * 1280 + (((kk*2 + hl) ^ (row & 7)) << 4));
        }
    }
    // B fragment pointer: per warp covers n-octets j = wn*4 + nt
    const uint4* __restrict__ wf = ((const uint4*)wfrag_dev) + (uint32_t)(wn * 4 * 64 + lane);

    // ---- prologue: bias + f into SMEM ----
    for (int i = tid; i < VP; i += NTHREADS) bias_s[i] = (i < VC) ? b_joint[i] : 0.f;
    for (int i = tid; i < JH; i += NTHREADS) f_s[i] = frow[i];
    __syncthreads();

    // ---- build A = relu(f + g) bf16 into swizzled SMEM ----
    for (int i = tid; i < 128 * 320; i += NTHREADS) {
        int u = i / 320, p = i - u * 320;
        const float2 gv = *(const float2*)(grow + (size_t)u * JH + 2 * p);
        float h0 = fmaxf(gv.x + f_s[2*p],     0.f);
        float h1 = fmaxf(gv.y + f_s[2*p + 1], 0.f);
        uint32_t pk = pack_bf16x2(h0, h1);
        int chunk = p >> 2, row = u;
        int sc = (chunk & ~7) | ((chunk & 7) ^ (row & 7));
        *(uint32_t*)(sb + A_OFF + row * 1280 + sc * 16 + (p & 3) * 4) = pk;
    }
    __syncthreads();   // A published; after this warps free-run

    // ---- main loop: 9 chunks x 10 K-slices, NO block barriers inside ----
    float acc[2][4][4];
    float sums[2][2];
#pragma unroll
    for (int mt = 0; mt < 2; mt++)
#pragma unroll
        for (int h = 0; h < 2; h++) sums[mt][h] = 0.f;

    for (int c = 0; c < NCHUNK; c++) {
#pragma unroll
        for (int mt = 0; mt < 2; mt++)
#pragma unroll
            for (int nt = 0; nt < 4; nt++)
#pragma unroll
                for (int k = 0; k < 4; k++) acc[mt][nt][k] = 0.f;

#pragma unroll 1
        for (int ks = 0; ks < NSLICE; ks++) {
            int s = c * NSLICE + ks;
            // B fragments for this slice: 8 coalesced LDG.128 into registers
            const uint4* ws = wf + (uint32_t)s * 1024;
            uint4 bq[4][2];
#pragma unroll
            for (int nt = 0; nt < 4; nt++) {
                bq[nt][0] = ws[nt * 64];
                bq[nt][1] = ws[nt * 64 + 32];
            }

            uint32_t aslice = a_base + (uint32_t)(ks * 128);
            // A register double-buffer over kk
            uint32_t afr[2][2][4];
            ldsm_x4(afr[0][0][0], afr[0][0][1], afr[0][0][2], afr[0][0][3], aslice + pA[0]);
            ldsm_x4(afr[0][1][0], afr[0][1][1], afr[0][1][2], afr[0][1][3], aslice + pA[4]);
#pragma unroll
            for (int kk = 0; kk < 4; kk++) {
                int cur = kk & 1;
                if (kk < 3) {
                    ldsm_x4(afr[cur^1][0][0], afr[cur^1][0][1], afr[cur^1][0][2], afr[cur^1][0][3],
                            aslice + pA[kk + 1]);
                    ldsm_x4(afr[cur^1][1][0], afr[cur^1][1][1], afr[cur^1][1][2], afr[cur^1][1][3],
                            aslice + pA[4 + kk + 1]);
                }
#pragma unroll
                for (int nt = 0; nt < 4; nt++) {
                    uint32_t b0, b1;
                    if ((kk & 1) == 0) { b0 = bq[nt][kk >> 1].x; b1 = bq[nt][kk >> 1].y; }
                    else               { b0 = bq[nt][kk >> 1].z; b1 = bq[nt][kk >> 1].w; }
#pragma unroll
                    for (int mt = 0; mt < 2; mt++)
                        mma16816(acc[mt][nt], afr[cur][mt], b0, b1);
                }
            }
        }

        // ---- epilogue: bias add, raw logit store, register exp-sum ----
#pragma unroll
        for (int mt = 0; mt < 2; mt++) {
#pragma unroll
            for (int h = 0; h < 2; h++) {
                int u = wm * 32 + mt * 16 + h * 8 + g;
                float* rb = out + obase + (size_t)u * VC;
#pragma unroll
                for (int nt = 0; nt < 4; nt++) {
                    int v = c * NC + wn * 32 + nt * 8 + q * 2;
                    float l0 = acc[mt][nt][h*2 + 0] + bias_s[v];
                    float l1 = acc[mt][nt][h*2 + 1] + bias_s[v + 1];
                    if (v + 1 < VC) {
                        rb[v] = l0; rb[v + 1] = l1;
                        sums[mt][h] += __expf(l0) + __expf(l1);
                    } else if (v < VC) {
                        rb[v] = l0;
                        sums[mt][h] += __expf(l0);
                    }
                }
            }
        }
        __syncthreads();   // bound warp drift (9 total) to keep B L1-resident
    }

    // ---- final per-row logsumexp ----
#pragma unroll
    for (int mt = 0; mt < 2; mt++) {
#pragma unroll
        for (int h = 0; h < 2; h++) {
            float s = sums[mt][h];
            s += __shfl_xor_sync(0xFFFFFFFF, s, 1);
            s += __shfl_xor_sync(0xFFFFFFFF, s, 2);
            if (q == 0) red[wn * 128 + wm * 32 + mt * 16 + h * 8 + g] = s;
        }
    }
    __syncthreads();
    if (tid < 128) {
        float s = red[tid] + red[128 + tid] + red[256 + tid] + red[384 + tid];
        lse_s[tid] = __logf(s);
    }
    __syncthreads();

    // ---- fixup: subtract lse (region is L2-hot) ----
    for (int u = 0; u < UU; u++) {
        float l = lse_s[u];
        float* rb = out + obase + (size_t)u * VC;
        for (int i = tid; i < VC; i += NTHREADS) rb[i] -= l;
    }
}

// ===================== launch ================================
extern "C" void kernel_launch(void* const* d_in, const int* in_sizes, int n_in,
                              void* d_out, int out_size) {
    const float* enc     = (const float*)d_in[0];
    const float* dec     = (const float*)d_in[1];
    const float* W_enc   = (const float*)d_in[2];
    const float* b_enc   = (const float*)d_in[3];
    const float* W_pred  = (const float*)d_in[4];
    const float* b_pred  = (const float*)d_in[5];
    const float* W_joint = (const float*)d_in[6];
    const float* b_joint = (const float*)d_in[7];
    float* out = (float*)d_out;

    cudaFuncSetAttribute(joint_kernel, cudaFuncAttributeMaxDynamicSharedMemorySize, DYN_SMEM);

    float *f_ptr, *g_ptr;
    cudaGetSymbolAddress((void**)&f_ptr, f_dev);
    cudaGetSymbolAddress((void**)&g_ptr, g_dev);

    wconv_kernel<<<(WFRAG_U32 + 255)/256, 256>>>(W_joint);
    proj_kernel<<<dim3(TT/32, JH/64, BB), 256>>>(enc, W_enc, b_enc, f_ptr, ENC_H, TT);
    proj_kernel<<<dim3(UU/32, JH/64, BB), 256>>>(dec, W_pred, b_pred, g_ptr, PRED_H, UU);
    joint_kernel<<<BB*TT, NTHREADS, DYN_SMEM>>>(b_joint, out);
}

// round 8
// speedup vs baseline: 1.4764x; 1.0073x over previous
#include <cuda_runtime.h>
#include <cuda_bf16.h>
#include <cstdint>
#include <math.h>

// ===================== problem constants =====================
#define BB 4
#define TT 256
#define UU 128
#define ENC_H 512
#define PRED_H 640
#define JH 640
#define VC 1025            // real classes
#define VP 1152            // padded classes (9 * 128)
#define NCHUNK 9
#define NC 128             // classes per chunk
#define NSLICE 20          // K slices of 32 per chunk
#define NSL_TOT 180        // total K32 slices
#define NTHREADS 512
#define WFRAG_U32 (90*16*2*32*4)   // 368640 uint32 = 1.47 MB (64k-slice records)

// ===================== device scratch ========================
__device__ float f_dev[BB*TT*JH];
__device__ float g_dev[BB*UU*JH];
__device__ uint32_t wfrag_dev[WFRAG_U32];   // W_joint in MMA-fragment order

// ===================== helpers ===========================
__device__ __forceinline__ uint32_t smem_to_u32(const void* p) {
    uint32_t a;
    asm("{ .reg .u64 t; cvta.to.shared.u64 t, %1; cvt.u32.u64 %0, t; }" : "=r"(a) : "l"(p));
    return a;
}
__device__ __forceinline__ uint32_t pack_bf16x2(float lo, float hi) {
    uint32_t p;
    asm("cvt.rn.bf16x2.f32 %0, %1, %2;" : "=r"(p) : "f"(hi), "f"(lo));
    return p;
}
__device__ __forceinline__ void ldsm_x4(uint32_t& r0, uint32_t& r1, uint32_t& r2, uint32_t& r3, uint32_t addr) {
    asm volatile("ldmatrix.sync.aligned.m8n8.x4.shared.b16 {%0,%1,%2,%3}, [%4];"
        : "=r"(r0), "=r"(r1), "=r"(r2), "=r"(r3) : "r"(addr));
}
__device__ __forceinline__ void mma16816(float* d, const uint32_t* a, uint32_t b0, uint32_t b1) {
    asm volatile("mma.sync.aligned.m16n8k16.row.col.f32.bf16.bf16.f32 "
        "{%0,%1,%2,%3}, {%4,%5,%6,%7}, {%8,%9}, {%0,%1,%2,%3};"
        : "+f"(d[0]), "+f"(d[1]), "+f"(d[2]), "+f"(d[3])
        : "r"(a[0]), "r"(a[1]), "r"(a[2]), "r"(a[3]), "r"(b0), "r"(b1));
}

// ===================== SMEM layout (relative to 1KB-aligned base) ==========
#define A_OFF      0                   // 128 x 640 bf16 swizzled: 163840 B
#define BIAS_OFF   163840              // 1152 fp32
#define F_OFF      168448              // 640 fp32
#define RED_OFF    171008              // 4 x 128 fp32
#define LSE_OFF    173056              // 128 fp32
#define SMEM_USED  173568
#define DYN_SMEM   (SMEM_USED + 1024)

// ===================== small projection GEMM (f and g) ======================
__global__ void proj_kernel(const float* __restrict__ X, const float* __restrict__ W,
                            const float* __restrict__ bias, float* __restrict__ Out,
                            int H, int R) {
    __shared__ float Xs[32*33];
    __shared__ float Ws[32*65];
    int r0 = blockIdx.x * 32, j0 = blockIdx.y * 64, b = blockIdx.z;
    int tid = threadIdx.x;
    int r = tid & 31, jg = tid >> 5;
    float acc[8];
#pragma unroll
    for (int i = 0; i < 8; i++) acc[i] = 0.f;
    const float* Xb = X + (size_t)b * H * R;
    for (int h0 = 0; h0 < H; h0 += 32) {
        for (int i = tid; i < 32*32; i += 256) {
            int hh = i >> 5, rr = i & 31;
            Xs[hh*33 + rr] = Xb[(size_t)(h0 + hh) * R + r0 + rr];
        }
        for (int i = tid; i < 64*32; i += 256) {
            int jj = i >> 5, hh = i & 31;
            Ws[hh*65 + jj] = W[(size_t)(j0 + jj) * H + h0 + hh];
        }
        __syncthreads();
#pragma unroll
        for (int hh = 0; hh < 32; hh++) {
            float x = Xs[hh*33 + r];
#pragma unroll
            for (int jj = 0; jj < 8; jj++)
                acc[jj] = fmaf(x, Ws[hh*65 + jg*8 + jj], acc[jj]);
        }
        __syncthreads();
    }
    float* o = Out + ((size_t)b * R + r0 + r) * JH + j0 + jg*8;
#pragma unroll
    for (int jj = 0; jj < 8; jj++) o[jj] = acc[jj] + bias[j0 + jg*8 + jj];
}

// ===================== W_joint fp32 -> bf16 fragment order ==================
// Layout (uint4 granularity): u4_index = ((s64*16 + j)*2 + h)*32 + lane
//   s64 = 64k slice (c*10+ks64), j = n-octet (0..15), h = k32 half, lane.
// Component q of the uint4 = bf16x2 {B[v][k], B[v][k+1]} with
//   v = c*128 + j*8 + (lane>>2)
//   k = ks64*64 + (h*2 + (q>>1))*16 + (q&1)*8 + (lane&3)*2
__global__ void wconv_kernel(const float* __restrict__ Wj) {
    int i = blockIdx.x * 256 + threadIdx.x;
    if (i >= WFRAG_U32) return;
    int q   = i & 3;
    int u4  = i >> 2;
    int T   = u4 & 31;
    int rest = u4 >> 5;
    int h = rest & 1; rest >>= 1;
    int j = rest & 15;
    int s = rest >> 4;
    int c = s / 10, ks = s - c * 10;
    int v = c * 128 + j * 8 + (T >> 2);
    int k = ks * 64 + (h * 2 + (q >> 1)) * 16 + (q & 1) * 8 + (T & 3) * 2;
    float v0 = 0.f, v1 = 0.f;
    if (v < VC) {
        v0 = Wj[(size_t)v * JH + k];
        v1 = Wj[(size_t)v * JH + k + 1];
    }
    wfrag_dev[i] = pack_bf16x2(v0, v1);
}

// ===================== fused joint GEMM + log_softmax ======================
__global__ void __launch_bounds__(NTHREADS, 1)
joint_kernel(const float* __restrict__ b_joint, float* __restrict__ out) {
    extern __shared__ char smraw[];
    uint32_t sm_u = smem_to_u32(smraw);
    uint32_t pad = ((sm_u + 1023) & ~1023u) - sm_u;
    char* sb = smraw + pad;
    uint32_t sb_u = sm_u + pad;

    float* bias_s = (float*)(sb + BIAS_OFF);
    float* f_s    = (float*)(sb + F_OFF);
    float* red    = (float*)(sb + RED_OFF);
    float* lse_s  = (float*)(sb + LSE_OFF);
    uint32_t a_base = sb_u + A_OFF;

    int tid  = threadIdx.x;
    int lane = tid & 31, wid = tid >> 5;
    int wm = wid >> 2, wn = wid & 3;     // 4 x 4 warp grid
    int g = lane >> 2, q = lane & 3;

    int bt = blockIdx.x;                 // (b, t)
    int b  = bt >> 8;                    // T = 256
    size_t obase = (size_t)bt * (UU * VC);
    const float* grow = g_dev + (size_t)b * UU * JH;
    const float* frow = f_dev + (size_t)bt * JH;

    // ---- per-warp A ldsm addressing constants ----
    // addr(ks, kk, mt) = rowb[mt] + (ks>>1)*128 + (lv ^ r7s[mt])
    //   lv = ((ks&1)<<6) | (kk<<5) | hls,  hls = (lane>>4)<<4
    uint32_t rowb[2], r7s[2];
#pragma unroll
    for (int mt = 0; mt < 2; mt++) {
        int row = wm * 32 + mt * 16 + (lane & 15);
        rowb[mt] = a_base + (uint32_t)(row * 1280);
        r7s[mt]  = (uint32_t)((row & 7) << 4);
    }
    uint32_t hls = (uint32_t)((lane >> 4) << 4);

    // B fragment pointer: per warp covers n-octets j = wn*4 + nt
    const uint4* __restrict__ wf = ((const uint4*)wfrag_dev) + (uint32_t)(wn * 4 * 64 + lane);

    // ---- prologue: bias + f into SMEM ----
    for (int i = tid; i < VP; i += NTHREADS) bias_s[i] = (i < VC) ? b_joint[i] : 0.f;
    for (int i = tid; i < JH; i += NTHREADS) f_s[i] = frow[i];
    __syncthreads();

    // ---- build A = relu(f + g) bf16 into swizzled SMEM ----
    for (int i = tid; i < 128 * 320; i += NTHREADS) {
        int u = i / 320, p = i - u * 320;
        const float2 gv = *(const float2*)(grow + (size_t)u * JH + 2 * p);
        float h0 = fmaxf(gv.x + f_s[2*p],     0.f);
        float h1 = fmaxf(gv.y + f_s[2*p + 1], 0.f);
        uint32_t pk = pack_bf16x2(h0, h1);
        int chunk = p >> 2, row = u;
        int sc = (chunk & ~7) | ((chunk & 7) ^ (row & 7));
        *(uint32_t*)(sb + A_OFF + row * 1280 + sc * 16 + (p & 3) * 4) = pk;
    }
    __syncthreads();   // A published; after this warps free-run

    // ---- main loop: 9 chunks x 20 K32-slices, B double-buffer prefetch ----
    float acc[2][4][4];
    float sums[2][2];
#pragma unroll
    for (int mt = 0; mt < 2; mt++)
#pragma unroll
        for (int h = 0; h < 2; h++) sums[mt][h] = 0.f;

    uint4 bq[2][4];
    // preload slice 0 into parity 0
#pragma unroll
    for (int nt = 0; nt < 4; nt++) bq[0][nt] = wf[nt * 64];

    for (int c = 0; c < NCHUNK; c++) {
#pragma unroll
        for (int mt = 0; mt < 2; mt++)
#pragma unroll
            for (int nt = 0; nt < 4; nt++)
#pragma unroll
                for (int k = 0; k < 4; k++) acc[mt][nt][k] = 0.f;

#pragma unroll 2
        for (int ks = 0; ks < NSLICE; ks++) {
            int s = c * NSLICE + ks;
            int par = ks & 1;
            // prefetch slice s+1 into the other parity (B is (c,k)-indexed: use s)
            if (s + 1 < NSL_TOT) {
                int sn = s + 1;
                const uint4* wsn = wf + (uint32_t)((sn >> 1) * 1024 + (sn & 1) * 32);
#pragma unroll
                for (int nt = 0; nt < 4; nt++) bq[par ^ 1][nt] = wsn[nt * 64];
            }

            // A is k-indexed within the tile: use ks (NOT s)
            uint32_t hi = (uint32_t)((ks >> 1) * 128);
            uint32_t lb = (uint32_t)((ks & 1) << 6) | hls;
#pragma unroll
            for (int kk = 0; kk < 2; kk++) {
                uint32_t lv = lb | (kk << 5);
                uint32_t afr[2][4];
                ldsm_x4(afr[0][0], afr[0][1], afr[0][2], afr[0][3],
                        rowb[0] + hi + (lv ^ r7s[0]));
                ldsm_x4(afr[1][0], afr[1][1], afr[1][2], afr[1][3],
                        rowb[1] + hi + (lv ^ r7s[1]));
#pragma unroll
                for (int nt = 0; nt < 4; nt++) {
                    uint32_t b0 = kk ? bq[par][nt].z : bq[par][nt].x;
                    uint32_t b1 = kk ? bq[par][nt].w : bq[par][nt].y;
                    mma16816(acc[0][nt], afr[0], b0, b1);
                    mma16816(acc[1][nt], afr[1], b0, b1);
                }
            }
        }

        // ---- epilogue: bias add, raw logit store, register exp-sum ----
#pragma unroll
        for (int mt = 0; mt < 2; mt++) {
#pragma unroll
            for (int h = 0; h < 2; h++) {
                int u = wm * 32 + mt * 16 + h * 8 + g;
                float* rb = out + obase + (size_t)u * VC;
#pragma unroll
                for (int nt = 0; nt < 4; nt++) {
                    int v = c * NC + wn * 32 + nt * 8 + q * 2;
                    float l0 = acc[mt][nt][h*2 + 0] + bias_s[v];
                    float l1 = acc[mt][nt][h*2 + 1] + bias_s[v + 1];
                    if (v + 1 < VC) {
                        rb[v] = l0; rb[v + 1] = l1;
                        sums[mt][h] += __expf(l0) + __expf(l1);
                    } else if (v < VC) {
                        rb[v] = l0;
                        sums[mt][h] += __expf(l0);
                    }
                }
            }
        }
        __syncthreads();   // bound warp drift (9 total) to keep B L1-resident
    }

    // ---- final per-row logsumexp ----
#pragma unroll
    for (int mt = 0; mt < 2; mt++) {
#pragma unroll
        for (int h = 0; h < 2; h++) {
            float s = sums[mt][h];
            s += __shfl_xor_sync(0xFFFFFFFF, s, 1);
            s += __shfl_xor_sync(0xFFFFFFFF, s, 2);
            if (q == 0) red[wn * 128 + wm * 32 + mt * 16 + h * 8 + g] = s;
        }
    }
    __syncthreads();
    if (tid < 128) {
        float s = red[tid] + red[128 + tid] + red[256 + tid] + red[384 + tid];
        lse_s[tid] = __logf(s);
    }
    __syncthreads();

    // ---- fixup: subtract lse (region is L2-hot) ----
    for (int u = 0; u < UU; u++) {
        float l = lse_s[u];
        float* rb = out + obase + (size_t)u * VC;
        for (int i = tid; i < VC; i += NTHREADS) rb[i] -= l;
    }
}

// ===================== launch ================================
extern "C" void kernel_launch(void* const* d_in, const int* in_sizes, int n_in,
                              void* d_out, int out_size) {
    const float* enc     = (const float*)d_in[0];
    const float* dec     = (const float*)d_in[1];
    const float* W_enc   = (const float*)d_in[2];
    const float* b_enc   = (const float*)d_in[3];
    const float* W_pred  = (const float*)d_in[4];
    const float* b_pred  = (const float*)d_in[5];
    const float* W_joint = (const float*)d_in[6];
    const float* b_joint = (const float*)d_in[7];
    float* out = (float*)d_out;

    cudaFuncSetAttribute(joint_kernel, cudaFuncAttributeMaxDynamicSharedMemorySize, DYN_SMEM);

    float *f_ptr, *g_ptr;
    cudaGetSymbolAddress((void**)&f_ptr, f_dev);
    cudaGetSymbolAddress((void**)&g_ptr, g_dev);

    wconv_kernel<<<(WFRAG_U32 + 255)/256, 256>>>(W_joint);
    proj_kernel<<<dim3(TT/32, JH/64, BB), 256>>>(enc, W_enc, b_enc, f_ptr, ENC_H, TT);
    proj_kernel<<<dim3(UU/32, JH/64, BB), 256>>>(dec, W_pred, b_pred, g_ptr, PRED_H, UU);
    joint_kernel<<<BB*TT, NTHREADS, DYN_SMEM>>>(b_joint, out);
}

// round 10
// speedup vs baseline: 1.6597x; 1.1241x over previous
#include <cuda_runtime.h>
#include <cuda_bf16.h>
#include <cstdint>
#include <math.h>

// ===================== problem constants =====================
#define BB 4
#define TT 256
#define UU 128
#define ENC_H 512
#define PRED_H 640
#define JH 640
#define VC 1025            // real classes
#define VP 1152            // padded classes (9 * 128)
#define NCHUNK 9
#define NC 128             // classes per chunk
#define NSLICE 20          // K slices of 32 per chunk
#define NSL_TOT 180        // total K32 slices
#define NTHREADS 256
#define MROWS 64           // rows per CTA (half a (b,t) tile)
#define WFRAG_U32 (90*16*2*32*4)   // 368640 uint32 = 1.47 MB

// ===================== device scratch ========================
__device__ float f_dev[BB*TT*JH];
__device__ float g_dev[BB*UU*JH];
__device__ uint32_t wfrag_dev[WFRAG_U32];   // W_joint in MMA-fragment order

// ===================== helpers ===========================
__device__ __forceinline__ uint32_t smem_to_u32(const void* p) {
    uint32_t a;
    asm("{ .reg .u64 t; cvta.to.shared.u64 t, %1; cvt.u32.u64 %0, t; }" : "=r"(a) : "l"(p));
    return a;
}
__device__ __forceinline__ uint32_t pack_bf16x2(float lo, float hi) {
    uint32_t p;
    asm("cvt.rn.bf16x2.f32 %0, %1, %2;" : "=r"(p) : "f"(hi), "f"(lo));
    return p;
}
__device__ __forceinline__ void ldsm_x4(uint32_t& r0, uint32_t& r1, uint32_t& r2, uint32_t& r3, uint32_t addr) {
    asm volatile("ldmatrix.sync.aligned.m8n8.x4.shared.b16 {%0,%1,%2,%3}, [%4];"
        : "=r"(r0), "=r"(r1), "=r"(r2), "=r"(r3) : "r"(addr));
}
__device__ __forceinline__ void mma16816(float* d, const uint32_t* a, uint32_t b0, uint32_t b1) {
    asm volatile("mma.sync.aligned.m16n8k16.row.col.f32.bf16.bf16.f32 "
        "{%0,%1,%2,%3}, {%4,%5,%6,%7}, {%8,%9}, {%0,%1,%2,%3};"
        : "+f"(d[0]), "+f"(d[1]), "+f"(d[2]), "+f"(d[3])
        : "r"(a[0]), "r"(a[1]), "r"(a[2]), "r"(a[3]), "r"(b0), "r"(b1));
}

// ===================== SMEM layout (relative to 1KB-aligned base) ==========
#define A_OFF      0                   // 64 x 640 bf16 swizzled: 81920 B
#define BIAS_OFF   81920               // 1152 fp32
#define F_OFF      86528               // 640 fp32
#define RED_OFF    89088               // 4 x 64 fp32
#define LSE_OFF    90112               // 64 fp32
#define SMEM_USED  90368
#define DYN_SMEM   (SMEM_USED + 1024)

// ===================== small projection GEMM (f and g) ======================
__global__ void proj_kernel(const float* __restrict__ X, const float* __restrict__ W,
                            const float* __restrict__ bias, float* __restrict__ Out,
                            int H, int R) {
    __shared__ float Xs[32*33];
    __shared__ float Ws[32*65];
    int r0 = blockIdx.x * 32, j0 = blockIdx.y * 64, b = blockIdx.z;
    int tid = threadIdx.x;
    int r = tid & 31, jg = tid >> 5;
    float acc[8];
#pragma unroll
    for (int i = 0; i < 8; i++) acc[i] = 0.f;
    const float* Xb = X + (size_t)b * H * R;
    for (int h0 = 0; h0 < H; h0 += 32) {
        for (int i = tid; i < 32*32; i += 256) {
            int hh = i >> 5, rr = i & 31;
            Xs[hh*33 + rr] = Xb[(size_t)(h0 + hh) * R + r0 + rr];
        }
        for (int i = tid; i < 64*32; i += 256) {
            int jj = i >> 5, hh = i & 31;
            Ws[hh*65 + jj] = W[(size_t)(j0 + jj) * H + h0 + hh];
        }
        __syncthreads();
#pragma unroll
        for (int hh = 0; hh < 32; hh++) {
            float x = Xs[hh*33 + r];
#pragma unroll
            for (int jj = 0; jj < 8; jj++)
                acc[jj] = fmaf(x, Ws[hh*65 + jg*8 + jj], acc[jj]);
        }
        __syncthreads();
    }
    float* o = Out + ((size_t)b * R + r0 + r) * JH + j0 + jg*8;
#pragma unroll
    for (int jj = 0; jj < 8; jj++) o[jj] = acc[jj] + bias[j0 + jg*8 + jj];
}

// ===================== W_joint fp32 -> bf16 fragment order ==================
__global__ void wconv_kernel(const float* __restrict__ Wj) {
    int i = blockIdx.x * 256 + threadIdx.x;
    if (i >= WFRAG_U32) return;
    int q   = i & 3;
    int u4  = i >> 2;
    int T   = u4 & 31;
    int rest = u4 >> 5;
    int h = rest & 1; rest >>= 1;
    int j = rest & 15;
    int s = rest >> 4;
    int c = s / 10, ks = s - c * 10;
    int v = c * 128 + j * 8 + (T >> 2);
    int k = ks * 64 + (h * 2 + (q >> 1)) * 16 + (q & 1) * 8 + (T & 3) * 2;
    float v0 = 0.f, v1 = 0.f;
    if (v < VC) {
        v0 = Wj[(size_t)v * JH + k];
        v1 = Wj[(size_t)v * JH + k + 1];
    }
    wfrag_dev[i] = pack_bf16x2(v0, v1);
}

// ===================== fused joint GEMM + log_softmax ======================
// One CTA = 64 rows (half a (b,t) tile); 2 CTAs co-resident per SM.
__global__ void __launch_bounds__(NTHREADS, 2)
joint_kernel(const float* __restrict__ b_joint, float* __restrict__ out) {
    extern __shared__ char smraw[];
    uint32_t sm_u = smem_to_u32(smraw);
    uint32_t pad = ((sm_u + 1023) & ~1023u) - sm_u;
    char* sb = smraw + pad;
    uint32_t sb_u = sm_u + pad;

    float* bias_s = (float*)(sb + BIAS_OFF);
    float* f_s    = (float*)(sb + F_OFF);
    float* red    = (float*)(sb + RED_OFF);
    float* lse_s  = (float*)(sb + LSE_OFF);
    uint32_t a_base = sb_u + A_OFF;

    int tid  = threadIdx.x;
    int lane = tid & 31, wid = tid >> 5;
    int wm = wid >> 2, wn = wid & 3;     // 2 x 4 warp grid (64 rows)
    int g = lane >> 2, q = lane & 3;

    int bt   = blockIdx.x >> 1;          // (b, t)
    int half = blockIdx.x & 1;           // which 64-row half of U
    int b    = bt >> 8;                  // T = 256
    size_t obase = (size_t)bt * (UU * VC) + (size_t)half * MROWS * VC;
    const float* grow = g_dev + (size_t)b * UU * JH + (size_t)half * MROWS * JH;
    const float* frow = f_dev + (size_t)bt * JH;

    // ---- per-warp A ldsm addressing constants ----
    uint32_t rowb[2], r7s[2];
#pragma unroll
    for (int mt = 0; mt < 2; mt++) {
        int row = wm * 32 + mt * 16 + (lane & 15);    // local row 0..63
        rowb[mt] = a_base + (uint32_t)(row * 1280);
        r7s[mt]  = (uint32_t)((row & 7) << 4);
    }
    uint32_t hls = (uint32_t)((lane >> 4) << 4);

    // B fragment pointer: per warp covers n-octets j = wn*4 + nt
    const uint4* __restrict__ wf = ((const uint4*)wfrag_dev) + (uint32_t)(wn * 4 * 64 + lane);

    // ---- prologue: bias + f into SMEM ----
    for (int i = tid; i < VP; i += NTHREADS) bias_s[i] = (i < VC) ? b_joint[i] : 0.f;
    for (int i = tid; i < JH; i += NTHREADS) f_s[i] = frow[i];
    __syncthreads();

    // ---- build A = relu(f + g) bf16 into swizzled SMEM (64 rows) ----
    for (int i = tid; i < MROWS * 320; i += NTHREADS) {
        int u = i / 320, p = i - u * 320;
        const float2 gv = *(const float2*)(grow + (size_t)u * JH + 2 * p);
        float h0 = fmaxf(gv.x + f_s[2*p],     0.f);
        float h1 = fmaxf(gv.y + f_s[2*p + 1], 0.f);
        uint32_t pk = pack_bf16x2(h0, h1);
        int chunk = p >> 2, row = u;
        int sc = (chunk & ~7) | ((chunk & 7) ^ (row & 7));
        *(uint32_t*)(sb + A_OFF + row * 1280 + sc * 16 + (p & 3) * 4) = pk;
    }
    __syncthreads();   // A published; after this warps free-run

    // ---- main loop: 9 chunks x 20 K32-slices, B double-buffer prefetch ----
    float acc[2][4][4];
    float sums[2][2];
#pragma unroll
    for (int mt = 0; mt < 2; mt++)
#pragma unroll
        for (int h = 0; h < 2; h++) sums[mt][h] = 0.f;

    uint4 bq[2][4];
#pragma unroll
    for (int nt = 0; nt < 4; nt++) bq[0][nt] = wf[nt * 64];

    for (int c = 0; c < NCHUNK; c++) {
#pragma unroll
        for (int mt = 0; mt < 2; mt++)
#pragma unroll
            for (int nt = 0; nt < 4; nt++)
#pragma unroll
                for (int k = 0; k < 4; k++) acc[mt][nt][k] = 0.f;

#pragma unroll 2
        for (int ks = 0; ks < NSLICE; ks++) {
            int s = c * NSLICE + ks;
            int par = ks & 1;
            // prefetch slice s+1 into the other parity (B is (c,k)-indexed: use s)
            if (s + 1 < NSL_TOT) {
                int sn = s + 1;
                const uint4* wsn = wf + (uint32_t)((sn >> 1) * 1024 + (sn & 1) * 32);
#pragma unroll
                for (int nt = 0; nt < 4; nt++) bq[par ^ 1][nt] = wsn[nt * 64];
            }

            // A is k-indexed within the tile: use ks
            uint32_t hi = (uint32_t)((ks >> 1) * 128);
            uint32_t lb = (uint32_t)((ks & 1) << 6) | hls;
#pragma unroll
            for (int kk = 0; kk < 2; kk++) {
                uint32_t lv = lb | (kk << 5);
                uint32_t afr[2][4];
                ldsm_x4(afr[0][0], afr[0][1], afr[0][2], afr[0][3],
                        rowb[0] + hi + (lv ^ r7s[0]));
                ldsm_x4(afr[1][0], afr[1][1], afr[1][2], afr[1][3],
                        rowb[1] + hi + (lv ^ r7s[1]));
#pragma unroll
                for (int nt = 0; nt < 4; nt++) {
                    uint32_t b0 = kk ? bq[par][nt].z : bq[par][nt].x;
                    uint32_t b1 = kk ? bq[par][nt].w : bq[par][nt].y;
                    mma16816(acc[0][nt], afr[0], b0, b1);
                    mma16816(acc[1][nt], afr[1], b0, b1);
                }
            }
        }

        // ---- epilogue: bias add, raw logit store (scalar: rows are odd-aligned),
        //      register exp-sum ----
#pragma unroll
        for (int mt = 0; mt < 2; mt++) {
#pragma unroll
            for (int h = 0; h < 2; h++) {
                int u = wm * 32 + mt * 16 + h * 8 + g;
                float* rb = out + obase + (size_t)u * VC;
#pragma unroll
                for (int nt = 0; nt < 4; nt++) {
                    int v = c * NC + wn * 32 + nt * 8 + q * 2;
                    float l0 = acc[mt][nt][h*2 + 0] + bias_s[v];
                    float l1 = acc[mt][nt][h*2 + 1] + bias_s[v + 1];
                    if (v + 1 < VC) {
                        rb[v] = l0; rb[v + 1] = l1;
                        sums[mt][h] += __expf(l0) + __expf(l1);
                    } else if (v < VC) {
                        rb[v] = l0;
                        sums[mt][h] += __expf(l0);
                    }
                }
            }
        }
        __syncthreads();   // bound warp drift within this CTA only (8 warps)
    }

    // ---- final per-row logsumexp ----
#pragma unroll
    for (int mt = 0; mt < 2; mt++) {
#pragma unroll
        for (int h = 0; h < 2; h++) {
            float s = sums[mt][h];
            s += __shfl_xor_sync(0xFFFFFFFF, s, 1);
            s += __shfl_xor_sync(0xFFFFFFFF, s, 2);
            if (q == 0) red[wn * MROWS + wm * 32 + mt * 16 + h * 8 + g] = s;
        }
    }
    __syncthreads();
    if (tid < MROWS) {
        float s = red[tid] + red[MROWS + tid] + red[2*MROWS + tid] + red[3*MROWS + tid];
        lse_s[tid] = __logf(s);
    }
    __syncthreads();

    // ---- fixup: subtract lse (region is L2-hot) ----
    for (int u = 0; u < MROWS; u++) {
        float l = lse_s[u];
        float* rb = out + obase + (size_t)u * VC;
        for (int i = tid; i < VC; i += NTHREADS) rb[i] -= l;
    }
}

// ===================== launch ================================
extern "C" void kernel_launch(void* const* d_in, const int* in_sizes, int n_in,
                              void* d_out, int out_size) {
    const float* enc     = (const float*)d_in[0];
    const float* dec     = (const float*)d_in[1];
    const float* W_enc   = (const float*)d_in[2];
    const float* b_enc   = (const float*)d_in[3];
    const float* W_pred  = (const float*)d_in[4];
    const float* b_pred  = (const float*)d_in[5];
    const float* W_joint = (const float*)d_in[6];
    const float* b_joint = (const float*)d_in[7];
    float* out = (float*)d_out;

    cudaFuncSetAttribute(joint_kernel, cudaFuncAttributeMaxDynamicSharedMemorySize, DYN_SMEM);

    float *f_ptr, *g_ptr;
    cudaGetSymbolAddress((void**)&f_ptr, f_dev);
    cudaGetSymbolAddress((void**)&g_ptr, g_dev);

    wconv_kernel<<<(WFRAG_U32 + 255)/256, 256>>>(W_joint);
    proj_kernel<<<dim3(TT/32, JH/64, BB), 256>>>(enc, W_enc, b_enc, f_ptr, ENC_H, TT);
    proj_kernel<<<dim3(UU/32, JH/64, BB), 256>>>(dec, W_pred, b_pred, g_ptr, PRED_H, UU);
    joint_kernel<<<BB*TT*2, NTHREADS, DYN_SMEM>>>(b_joint, out);
}

// round 11
// speedup vs baseline: 2.2362x; 1.3474x over previous
#include <cuda_runtime.h>
#include <cuda_bf16.h>
#include <cstdint>
#include <math.h>

// ===================== problem constants =====================
#define BB 4
#define TT 256
#define UU 128
#define ENC_H 512
#define PRED_H 640
#define JH 640
#define VC 1025            // real classes
#define VP 1152            // padded classes (9 * 128)
#define NCHUNK 9
#define NC 128             // classes per chunk
#define NSLICE 20          // K slices of 32 per chunk
#define NSL_TOT 180        // total K32 slices
#define NTHREADS 128
#define MROWS 32           // rows per CTA (quarter of a (b,t) tile)
#define WFRAG_U32 (90*16*2*32*4)   // 368640 uint32 = 1.47 MB

// ===================== device scratch ========================
__device__ float f_dev[BB*TT*JH];
__device__ float g_dev[BB*UU*JH];
__device__ uint32_t wfrag_dev[WFRAG_U32];   // W_joint in MMA-fragment order

// ===================== helpers ===========================
__device__ __forceinline__ uint32_t smem_to_u32(const void* p) {
    uint32_t a;
    asm("{ .reg .u64 t; cvta.to.shared.u64 t, %1; cvt.u32.u64 %0, t; }" : "=r"(a) : "l"(p));
    return a;
}
__device__ __forceinline__ uint32_t pack_bf16x2(float lo, float hi) {
    uint32_t p;
    asm("cvt.rn.bf16x2.f32 %0, %1, %2;" : "=r"(p) : "f"(hi), "f"(lo));
    return p;
}
__device__ __forceinline__ void ldsm_x4(uint32_t& r0, uint32_t& r1, uint32_t& r2, uint32_t& r3, uint32_t addr) {
    asm volatile("ldmatrix.sync.aligned.m8n8.x4.shared.b16 {%0,%1,%2,%3}, [%4];"
        : "=r"(r0), "=r"(r1), "=r"(r2), "=r"(r3) : "r"(addr));
}
__device__ __forceinline__ void mma16816(float* d, const uint32_t* a, uint32_t b0, uint32_t b1) {
    asm volatile("mma.sync.aligned.m16n8k16.row.col.f32.bf16.bf16.f32 "
        "{%0,%1,%2,%3}, {%4,%5,%6,%7}, {%8,%9}, {%0,%1,%2,%3};"
        : "+f"(d[0]), "+f"(d[1]), "+f"(d[2]), "+f"(d[3])
        : "r"(a[0]), "r"(a[1]), "r"(a[2]), "r"(a[3]), "r"(b0), "r"(b1));
}

// ===================== SMEM layout (relative to 1KB-aligned base) ==========
#define A_OFF      0                   // 32 x 640 bf16 swizzled: 40960 B
#define BIAS_OFF   40960               // 1152 fp32
#define F_OFF      45568               // 640 fp32
#define RED_OFF    48128               // 4 x 32 fp32
#define LSE_OFF    48640               // 32 fp32
#define SMEM_USED  48768
#define DYN_SMEM   (SMEM_USED + 1024)

// ===================== small projection GEMM (f and g) ======================
__global__ void proj_kernel(const float* __restrict__ X, const float* __restrict__ W,
                            const float* __restrict__ bias, float* __restrict__ Out,
                            int H, int R) {
    __shared__ float Xs[32*33];
    __shared__ float Ws[32*65];
    int r0 = blockIdx.x * 32, j0 = blockIdx.y * 64, b = blockIdx.z;
    int tid = threadIdx.x;
    int r = tid & 31, jg = tid >> 5;
    float acc[8];
#pragma unroll
    for (int i = 0; i < 8; i++) acc[i] = 0.f;
    const float* Xb = X + (size_t)b * H * R;
    for (int h0 = 0; h0 < H; h0 += 32) {
        for (int i = tid; i < 32*32; i += 256) {
            int hh = i >> 5, rr = i & 31;
            Xs[hh*33 + rr] = Xb[(size_t)(h0 + hh) * R + r0 + rr];
        }
        for (int i = tid; i < 64*32; i += 256) {
            int jj = i >> 5, hh = i & 31;
            Ws[hh*65 + jj] = W[(size_t)(j0 + jj) * H + h0 + hh];
        }
        __syncthreads();
#pragma unroll
        for (int hh = 0; hh < 32; hh++) {
            float x = Xs[hh*33 + r];
#pragma unroll
            for (int jj = 0; jj < 8; jj++)
                acc[jj] = fmaf(x, Ws[hh*65 + jg*8 + jj], acc[jj]);
        }
        __syncthreads();
    }
    float* o = Out + ((size_t)b * R + r0 + r) * JH + j0 + jg*8;
#pragma unroll
    for (int jj = 0; jj < 8; jj++) o[jj] = acc[jj] + bias[j0 + jg*8 + jj];
}

// ===================== W_joint fp32 -> bf16 fragment order ==================
__global__ void wconv_kernel(const float* __restrict__ Wj) {
    int i = blockIdx.x * 256 + threadIdx.x;
    if (i >= WFRAG_U32) return;
    int q   = i & 3;
    int u4  = i >> 2;
    int T   = u4 & 31;
    int rest = u4 >> 5;
    int h = rest & 1; rest >>= 1;
    int j = rest & 15;
    int s = rest >> 4;
    int c = s / 10, ks = s - c * 10;
    int v = c * 128 + j * 8 + (T >> 2);
    int k = ks * 64 + (h * 2 + (q >> 1)) * 16 + (q & 1) * 8 + (T & 3) * 2;
    float v0 = 0.f, v1 = 0.f;
    if (v < VC) {
        v0 = Wj[(size_t)v * JH + k];
        v1 = Wj[(size_t)v * JH + k + 1];
    }
    wfrag_dev[i] = pack_bf16x2(v0, v1);
}

// ===================== fused joint GEMM + log_softmax ======================
// One CTA = 32 rows (quarter of a (b,t) tile); 4 CTAs co-resident per SM.
__global__ void __launch_bounds__(NTHREADS, 4)
joint_kernel(const float* __restrict__ b_joint, float* __restrict__ out) {
    extern __shared__ char smraw[];
    uint32_t sm_u = smem_to_u32(smraw);
    uint32_t pad = ((sm_u + 1023) & ~1023u) - sm_u;
    char* sb = smraw + pad;
    uint32_t sb_u = sm_u + pad;

    float* bias_s = (float*)(sb + BIAS_OFF);
    float* f_s    = (float*)(sb + F_OFF);
    float* red    = (float*)(sb + RED_OFF);
    float* lse_s  = (float*)(sb + LSE_OFF);
    uint32_t a_base = sb_u + A_OFF;

    int tid  = threadIdx.x;
    int lane = tid & 31, wid = tid >> 5;
    int wn = wid;                        // 1 x 4 warp grid (32 rows, 4 n-quarters)
    int g = lane >> 2, q = lane & 3;

    int bt   = blockIdx.x >> 2;          // (b, t)
    int quar = blockIdx.x & 3;           // which 32-row quarter of U
    int b    = bt >> 8;                  // T = 256
    size_t obase = (size_t)bt * (UU * VC) + (size_t)quar * MROWS * VC;
    const float* grow = g_dev + (size_t)b * UU * JH + (size_t)quar * MROWS * JH;
    const float* frow = f_dev + (size_t)bt * JH;

    // ---- per-warp A ldsm addressing constants ----
    uint32_t rowb[2], r7s[2];
#pragma unroll
    for (int mt = 0; mt < 2; mt++) {
        int row = mt * 16 + (lane & 15);    // local row 0..31
        rowb[mt] = a_base + (uint32_t)(row * 1280);
        r7s[mt]  = (uint32_t)((row & 7) << 4);
    }
    uint32_t hls = (uint32_t)((lane >> 4) << 4);

    // B fragment pointer: per warp covers n-octets j = wn*4 + nt
    const uint4* __restrict__ wf = ((const uint4*)wfrag_dev) + (uint32_t)(wn * 4 * 64 + lane);

    // ---- prologue: bias + f into SMEM ----
    for (int i = tid; i < VP; i += NTHREADS) bias_s[i] = (i < VC) ? b_joint[i] : 0.f;
    for (int i = tid; i < JH; i += NTHREADS) f_s[i] = frow[i];
    __syncthreads();

    // ---- build A = relu(f + g) bf16 into swizzled SMEM (32 rows) ----
    for (int i = tid; i < MROWS * 320; i += NTHREADS) {
        int u = i / 320, p = i - u * 320;
        const float2 gv = *(const float2*)(grow + (size_t)u * JH + 2 * p);
        float h0 = fmaxf(gv.x + f_s[2*p],     0.f);
        float h1 = fmaxf(gv.y + f_s[2*p + 1], 0.f);
        uint32_t pk = pack_bf16x2(h0, h1);
        int chunk = p >> 2, row = u;
        int sc = (chunk & ~7) | ((chunk & 7) ^ (row & 7));
        *(uint32_t*)(sb + A_OFF + row * 1280 + sc * 16 + (p & 3) * 4) = pk;
    }
    __syncthreads();   // A published; after this warps free-run

    // ---- main loop: 9 chunks x 20 K32-slices, B double-buffer prefetch ----
    float acc[2][4][4];
    float sums[2][2];
#pragma unroll
    for (int mt = 0; mt < 2; mt++)
#pragma unroll
        for (int h = 0; h < 2; h++) sums[mt][h] = 0.f;

    uint4 bq[2][4];
#pragma unroll
    for (int nt = 0; nt < 4; nt++) bq[0][nt] = wf[nt * 64];

    for (int c = 0; c < NCHUNK; c++) {
#pragma unroll
        for (int mt = 0; mt < 2; mt++)
#pragma unroll
            for (int nt = 0; nt < 4; nt++)
#pragma unroll
                for (int k = 0; k < 4; k++) acc[mt][nt][k] = 0.f;

#pragma unroll 2
        for (int ks = 0; ks < NSLICE; ks++) {
            int s = c * NSLICE + ks;
            int par = ks & 1;
            // prefetch slice s+1 into the other parity (B is (c,k)-indexed: use s)
            if (s + 1 < NSL_TOT) {
                int sn = s + 1;
                const uint4* wsn = wf + (uint32_t)((sn >> 1) * 1024 + (sn & 1) * 32);
#pragma unroll
                for (int nt = 0; nt < 4; nt++) bq[par ^ 1][nt] = wsn[nt * 64];
            }

            // A is k-indexed within the tile: use ks
            uint32_t hi = (uint32_t)((ks >> 1) * 128);
            uint32_t lb = (uint32_t)((ks & 1) << 6) | hls;
#pragma unroll
            for (int kk = 0; kk < 2; kk++) {
                uint32_t lv = lb | (kk << 5);
                uint32_t afr[2][4];
                ldsm_x4(afr[0][0], afr[0][1], afr[0][2], afr[0][3],
                        rowb[0] + hi + (lv ^ r7s[0]));
                ldsm_x4(afr[1][0], afr[1][1], afr[1][2], afr[1][3],
                        rowb[1] + hi + (lv ^ r7s[1]));
#pragma unroll
                for (int nt = 0; nt < 4; nt++) {
                    uint32_t b0 = kk ? bq[par][nt].z : bq[par][nt].x;
                    uint32_t b1 = kk ? bq[par][nt].w : bq[par][nt].y;
                    mma16816(acc[0][nt], afr[0], b0, b1);
                    mma16816(acc[1][nt], afr[1], b0, b1);
                }
            }
        }

        // ---- epilogue: bias add, raw logit store (scalar: rows odd-aligned),
        //      register exp-sum ----
#pragma unroll
        for (int mt = 0; mt < 2; mt++) {
#pragma unroll
            for (int h = 0; h < 2; h++) {
                int u = mt * 16 + h * 8 + g;
                float* rb = out + obase + (size_t)u * VC;
#pragma unroll
                for (int nt = 0; nt < 4; nt++) {
                    int v = c * NC + wn * 32 + nt * 8 + q * 2;
                    float l0 = acc[mt][nt][h*2 + 0] + bias_s[v];
                    float l1 = acc[mt][nt][h*2 + 1] + bias_s[v + 1];
                    if (v + 1 < VC) {
                        rb[v] = l0; rb[v + 1] = l1;
                        sums[mt][h] += __expf(l0) + __expf(l1);
                    } else if (v < VC) {
                        rb[v] = l0;
                        sums[mt][h] += __expf(l0);
                    }
                }
            }
        }
        __syncthreads();   // convoy only 4 warps of this CTA
    }

    // ---- final per-row logsumexp ----
#pragma unroll
    for (int mt = 0; mt < 2; mt++) {
#pragma unroll
        for (int h = 0; h < 2; h++) {
            float s = sums[mt][h];
            s += __shfl_xor_sync(0xFFFFFFFF, s, 1);
            s += __shfl_xor_sync(0xFFFFFFFF, s, 2);
            if (q == 0) red[wn * MROWS + mt * 16 + h * 8 + g] = s;
        }
    }
    __syncthreads();
    if (tid < MROWS) {
        float s = red[tid] + red[MROWS + tid] + red[2*MROWS + tid] + red[3*MROWS + tid];
        lse_s[tid] = __logf(s);
    }
    __syncthreads();

    // ---- fixup: subtract lse (region is L2-hot) ----
    for (int u = 0; u < MROWS; u++) {
        float l = lse_s[u];
        float* rb = out + obase + (size_t)u * VC;
        for (int i = tid; i < VC; i += NTHREADS) rb[i] -= l;
    }
}

// ===================== launch ================================
extern "C" void kernel_launch(void* const* d_in, const int* in_sizes, int n_in,
                              void* d_out, int out_size) {
    const float* enc     = (const float*)d_in[0];
    const float* dec     = (const float*)d_in[1];
    const float* W_enc   = (const float*)d_in[2];
    const float* b_enc   = (const float*)d_in[3];
    const float* W_pred  = (const float*)d_in[4];
    const float* b_pred  = (const float*)d_in[5];
    const float* W_joint = (const float*)d_in[6];
    const float* b_joint = (const float*)d_in[7];
    float* out = (float*)d_out;

    cudaFuncSetAttribute(joint_kernel, cudaFuncAttributeMaxDynamicSharedMemorySize, DYN_SMEM);

    float *f_ptr, *g_ptr;
    cudaGetSymbolAddress((void**)&f_ptr, f_dev);
    cudaGetSymbolAddress((void**)&g_ptr, g_dev);

    wconv_kernel<<<(WFRAG_U32 + 255)/256, 256>>>(W_joint);
    proj_kernel<<<dim3(TT/32, JH/64, BB), 256>>>(enc, W_enc, b_enc, f_ptr, ENC_H, TT);
    proj_kernel<<<dim3(UU/32, JH/64, BB), 256>>>(dec, W_pred, b_pred, g_ptr, PRED_H, UU);
    joint_kernel<<<BB*TT*4, NTHREADS, DYN_SMEM>>>(b_joint, out);
}